// round 2
// baseline (speedup 1.0000x reference)
#include <cuda_runtime.h>
#include <cuda_bf16.h>
#include <math.h>
#include <float.h>

// Problem constants
#define S    2048
#define D    4096         // H*HD
#define HQ   32           // query heads
#define G    8            // kv heads
#define HD   128
#define E    6144         // D + 2*G*HD
#define HG   4            // HQ / G
#define EPSF 1e-5f

// ---------------------------------------------------------------------------
// Scratch (device globals; no runtime allocation allowed)
// ---------------------------------------------------------------------------
__device__ float g_qkv[(size_t)S * E];                 // 50.3 MB
__device__ float g_scores[(size_t)HQ * S * S];         // 537 MB
__device__ float g_attn[(size_t)S * D];                // 33.6 MB
__device__ float g_cos[(size_t)S * (HD / 2)];
__device__ float g_sin[(size_t)S * (HD / 2)];

// ---------------------------------------------------------------------------
// RoPE cos/sin table.  Matches reference float32 semantics:
//   freq  = fl32( 1e6 ^ (-(2i)/128) )      (fp64 pow, rounded to fp32)
//   ang   = fl32( s * freq )               (fp32 multiply)
//   cos/sin = fl32( cos/sin(ang) )         (fp64 trig of the fp32 angle)
// ---------------------------------------------------------------------------
__global__ void rope_table_kernel(float* __restrict__ cosT, float* __restrict__ sinT) {
    int idx = blockIdx.x * blockDim.x + threadIdx.x;
    if (idx >= S * (HD / 2)) return;
    int s = idx >> 6;
    int i = idx & 63;
    double freq_d = pow(1.0e6, -(double)(2 * i) / 128.0);
    float  freq_f = (float)freq_d;
    float  ang    = (float)s * freq_f;
    double cd, sd;
    sincos((double)ang, &sd, &cd);
    cosT[idx] = (float)cd;
    sinT[idx] = (float)sd;
}

// ---------------------------------------------------------------------------
// Fused RMSNorm + RoPE, in place on q (32 heads) and k (8 heads) in g_qkv.
// One warp per (s, head) row of 128 elements.
// ---------------------------------------------------------------------------
__global__ void rmsnorm_rope_kernel(float* __restrict__ qkv,
                                    const float* __restrict__ qw,
                                    const float* __restrict__ kw,
                                    const float* __restrict__ cosT,
                                    const float* __restrict__ sinT) {
    int gwarp = (blockIdx.x * blockDim.x + threadIdx.x) >> 5;
    int lane  = threadIdx.x & 31;
    const int NROWS = S * (HQ + G);
    if (gwarp >= NROWS) return;

    int s  = gwarp / (HQ + G);
    int hh = gwarp % (HQ + G);

    float* row;
    const float* w;
    if (hh < HQ) { row = qkv + (long long)s * E + hh * HD;            w = qw; }
    else         { row = qkv + (long long)s * E + D + (hh - HQ) * HD; w = kw; }

    float2* row2 = (float2*)row;
    float2 a = row2[lane];
    float2 b = row2[lane + 32];

    float ss = a.x * a.x + a.y * a.y + b.x * b.x + b.y * b.y;
    #pragma unroll
    for (int o = 16; o; o >>= 1) ss += __shfl_xor_sync(0xFFFFFFFFu, ss, o);
    float r = rsqrtf(ss * (1.0f / 128.0f) + EPSF);

    const float2* w2 = (const float2*)w;
    float2 wa = w2[lane], wb = w2[lane + 32];

    float ax = (a.x * r) * wa.x, ay = (a.y * r) * wa.y;
    float bx = (b.x * r) * wb.x, by = (b.y * r) * wb.y;

    int base = s * (HD / 2);
    float c0 = cosT[base + lane],      s0 = sinT[base + lane];
    float c1 = cosT[base + lane + 32], s1 = sinT[base + lane + 32];

    row2[lane]      = make_float2(ax * c0 - ay * s0, ax * s0 + ay * c0);
    row2[lane + 32] = make_float2(bx * c1 - by * s1, bx * s1 + by * c1);
}

// ---------------------------------------------------------------------------
// Generic tiled SGEMM with register-staged double buffering.
//   C[m,n] = alpha * sum_k A[m,k] * B'[k,n]
//   BT=true : B row-major [N,K] (K contiguous)  -> C = A * B^T
//   BT=false: B row-major [K,N] (N contiguous)  -> C = A * B
//   CAUSAL 0: none
//   CAUSAL 1: skip fully-masked tiles (n0 >= m0+BM)   (QK^T)
//   CAUSAL 2: K-loop limited to min(K, m0+BM)         (P@V)
// Per-z pointer offsets; B's z index is z / bzdiv (GQA share).
// Tile 128x128x16, 256 threads, 8x8 per thread; dims are tile multiples here.
// ---------------------------------------------------------------------------
#define BMM 128
#define BNN 128
#define BKK 16
#define TM  8
#define TN  8

template <bool BT, int CAUSAL>
__global__ void __launch_bounds__(256)
sgemm_kernel(const float* __restrict__ Abase, const float* __restrict__ Bbase,
             float* __restrict__ Cbase,
             int M, int N, int K,
             int lda, int ldb, int ldc,
             long long sAz, long long sBz, long long sCz, int bzdiv,
             float alpha) {
    int z = blockIdx.z;
    const float* A = Abase + (long long)z * sAz;
    const float* B = Bbase + (long long)(z / bzdiv) * sBz;
    float*       C = Cbase + (long long)z * sCz;

    int m0 = blockIdx.y * BMM;
    int n0 = blockIdx.x * BNN;

    if (CAUSAL == 1 && n0 >= m0 + BMM) return;   // fully masked tile
    int Keff = (CAUSAL == 2) ? min(K, m0 + BMM) : K;

    __shared__ float As[2][BKK][BMM + 4];
    __shared__ float Bs[2][BKK][BNN + 4];

    int tid = threadIdx.x;
    int tm = tid >> 4;
    int tn = tid & 15;

    // per-thread load coordinates (two float4 loads per tile per operand)
    int arow0 = tid >> 2;            // 0..63
    int akg   = (tid & 3) * 4;       // 0,4,8,12
    // BT=false B loader coords
    int bkrow0 = tid >> 5;           // 0..7
    int bnc    = (tid & 31) * 4;     // 0..124

    float acc[TM][TN];
    #pragma unroll
    for (int i = 0; i < TM; i++)
        #pragma unroll
        for (int j = 0; j < TN; j++) acc[i][j] = 0.0f;

    // ---- prologue: load K-tile 0 straight to stage 0 ----
    {
        #pragma unroll
        for (int it = 0; it < 2; it++) {
            int row = arow0 + it * 64;
            float4 v = *(const float4*)(A + (long long)(m0 + row) * lda + akg);
            As[0][akg + 0][row] = v.x;
            As[0][akg + 1][row] = v.y;
            As[0][akg + 2][row] = v.z;
            As[0][akg + 3][row] = v.w;
        }
        if (BT) {
            #pragma unroll
            for (int it = 0; it < 2; it++) {
                int row = arow0 + it * 64;
                float4 v = *(const float4*)(B + (long long)(n0 + row) * ldb + akg);
                Bs[0][akg + 0][row] = v.x;
                Bs[0][akg + 1][row] = v.y;
                Bs[0][akg + 2][row] = v.z;
                Bs[0][akg + 3][row] = v.w;
            }
        } else {
            #pragma unroll
            for (int it = 0; it < 2; it++) {
                int krow = bkrow0 + it * 8;
                float4 v = *(const float4*)(B + (long long)krow * ldb + n0 + bnc);
                *(float4*)&Bs[0][krow][bnc] = v;
            }
        }
    }
    __syncthreads();

    int buf = 0;
    for (int k0 = 0; k0 < Keff; k0 += BKK) {
        bool has_next = (k0 + BKK) < Keff;
        float4 ra[2], rb[2];

        // ---- prefetch next K-tile into registers (long-latency loads first) ----
        if (has_next) {
            int kn = k0 + BKK;
            #pragma unroll
            for (int it = 0; it < 2; it++) {
                int row = arow0 + it * 64;
                ra[it] = *(const float4*)(A + (long long)(m0 + row) * lda + kn + akg);
            }
            if (BT) {
                #pragma unroll
                for (int it = 0; it < 2; it++) {
                    int row = arow0 + it * 64;
                    rb[it] = *(const float4*)(B + (long long)(n0 + row) * ldb + kn + akg);
                }
            } else {
                #pragma unroll
                for (int it = 0; it < 2; it++) {
                    int krow = bkrow0 + it * 8;
                    rb[it] = *(const float4*)(B + (long long)(kn + krow) * ldb + n0 + bnc);
                }
            }
        }

        // ---- compute on current stage ----
        #pragma unroll
        for (int kk = 0; kk < BKK; kk++) {
            float af[TM], bf[TN];
            float4 a0 = *(const float4*)&As[buf][kk][tm * TM];
            float4 a1 = *(const float4*)&As[buf][kk][tm * TM + 4];
            af[0] = a0.x; af[1] = a0.y; af[2] = a0.z; af[3] = a0.w;
            af[4] = a1.x; af[5] = a1.y; af[6] = a1.z; af[7] = a1.w;
            float4 b0 = *(const float4*)&Bs[buf][kk][tn * TN];
            float4 b1 = *(const float4*)&Bs[buf][kk][tn * TN + 4];
            bf[0] = b0.x; bf[1] = b0.y; bf[2] = b0.z; bf[3] = b0.w;
            bf[4] = b1.x; bf[5] = b1.y; bf[6] = b1.z; bf[7] = b1.w;
            #pragma unroll
            for (int i = 0; i < TM; i++)
                #pragma unroll
                for (int j = 0; j < TN; j++)
                    acc[i][j] += af[i] * bf[j];
        }

        // ---- commit prefetched tile to the other stage ----
        if (has_next) {
            int nb = buf ^ 1;
            #pragma unroll
            for (int it = 0; it < 2; it++) {
                int row = arow0 + it * 64;
                As[nb][akg + 0][row] = ra[it].x;
                As[nb][akg + 1][row] = ra[it].y;
                As[nb][akg + 2][row] = ra[it].z;
                As[nb][akg + 3][row] = ra[it].w;
            }
            if (BT) {
                #pragma unroll
                for (int it = 0; it < 2; it++) {
                    int row = arow0 + it * 64;
                    Bs[nb][akg + 0][row] = rb[it].x;
                    Bs[nb][akg + 1][row] = rb[it].y;
                    Bs[nb][akg + 2][row] = rb[it].z;
                    Bs[nb][akg + 3][row] = rb[it].w;
                }
            } else {
                #pragma unroll
                for (int it = 0; it < 2; it++) {
                    int krow = bkrow0 + it * 8;
                    *(float4*)&Bs[nb][krow][bnc] = rb[it];
                }
            }
            __syncthreads();
            buf = nb;
        }
    }

    #pragma unroll
    for (int i = 0; i < TM; i++) {
        int m = m0 + tm * TM + i;
        #pragma unroll
        for (int j = 0; j < TN; j += 4) {
            int n = n0 + tn * TN + j;
            float4 v = make_float4(acc[i][j + 0] * alpha, acc[i][j + 1] * alpha,
                                   acc[i][j + 2] * alpha, acc[i][j + 3] * alpha);
            *(float4*)(C + (long long)m * ldc + n) = v;
        }
    }
}

// ---------------------------------------------------------------------------
// Causal softmax over scores[h][s][0..s], in place. Also zero-fills
// (s, ceil128(s+1)) -- exactly the slack region read by the K-limited PV GEMM.
// One 256-thread block per (s, h) row; row held in registers.
// ---------------------------------------------------------------------------
__global__ void softmax_kernel(float* __restrict__ scores) {
    int s = blockIdx.x;
    int h = blockIdx.y;
    float* row = scores + ((long long)h * S + s) * (long long)S;
    int n    = s + 1;
    int nend = (n + 127) & ~127;
    int tid  = threadIdx.x;

    float v[8];
    float mx = -FLT_MAX;
    #pragma unroll
    for (int i = 0; i < 8; i++) {
        int t = tid + i * 256;
        v[i] = (t < n) ? row[t] : -FLT_MAX;
        mx = fmaxf(mx, v[i]);
    }

    __shared__ float red[8];
    #pragma unroll
    for (int o = 16; o; o >>= 1) mx = fmaxf(mx, __shfl_xor_sync(0xFFFFFFFFu, mx, o));
    if ((tid & 31) == 0) red[tid >> 5] = mx;
    __syncthreads();
    mx = red[0];
    #pragma unroll
    for (int w = 1; w < 8; w++) mx = fmaxf(mx, red[w]);
    __syncthreads();

    float sum = 0.0f;
    #pragma unroll
    for (int i = 0; i < 8; i++) {
        int t = tid + i * 256;
        v[i] = (t < n) ? expf(v[i] - mx) : 0.0f;
        sum += v[i];
    }
    #pragma unroll
    for (int o = 16; o; o >>= 1) sum += __shfl_xor_sync(0xFFFFFFFFu, sum, o);
    if ((tid & 31) == 0) red[tid >> 5] = sum;
    __syncthreads();
    float tot = red[0];
    #pragma unroll
    for (int w = 1; w < 8; w++) tot += red[w];
    float inv = 1.0f / tot;

    #pragma unroll
    for (int i = 0; i < 8; i++) {
        int t = tid + i * 256;
        if (t < n)         row[t] = v[i] * inv;
        else if (t < nend) row[t] = 0.0f;
    }
}

// ---------------------------------------------------------------------------
// Launch
// ---------------------------------------------------------------------------
extern "C" void kernel_launch(void* const* d_in, const int* in_sizes, int n_in,
                              void* d_out, int out_size) {
    const float* x     = (const float*)d_in[0];  // [1, 2048, 4096]
    const float* w_qkv = (const float*)d_in[1];  // [6144, 4096]
    const float* w_out = (const float*)d_in[2];  // [4096, 4096]
    const float* qw    = (const float*)d_in[3];  // [128]
    const float* kw    = (const float*)d_in[4];  // [128]
    float* out = (float*)d_out;                  // [1, 2048, 4096]

    float *qkv, *scores, *attn, *cosT, *sinT;
    cudaGetSymbolAddress((void**)&qkv,    g_qkv);
    cudaGetSymbolAddress((void**)&scores, g_scores);
    cudaGetSymbolAddress((void**)&attn,   g_attn);
    cudaGetSymbolAddress((void**)&cosT,   g_cos);
    cudaGetSymbolAddress((void**)&sinT,   g_sin);

    const float scale = 0.08838834764831845f;    // 1/sqrt(128)

    // 1. RoPE tables
    rope_table_kernel<<<(S * (HD / 2) + 255) / 256, 256>>>(cosT, sinT);

    // 2. QKV projection: qkv[s,e] = sum_d x[s,d] * w_qkv[e,d]
    {
        dim3 grid(E / BNN, S / BMM, 1);
        sgemm_kernel<true, 0><<<grid, 256>>>(x, w_qkv, qkv,
                                             S, E, D, D, D, E,
                                             0, 0, 0, 1, 1.0f);
    }

    // 3. RMSNorm + RoPE on q and k, in place
    {
        int nwarps = S * (HQ + G);
        rmsnorm_rope_kernel<<<nwarps / 8, 256>>>(qkv, qw, kw, cosT, sinT);
    }

    // 4. scores[h] = scale * Q_h @ K_{h/4}^T   (causal tile-skip)
    {
        dim3 grid(S / BNN, S / BMM, HQ);
        sgemm_kernel<true, 1><<<grid, 256>>>(qkv, qkv + D, scores,
                                             S, S, HD, E, E, S,
                                             HD, HD, (long long)S * S, HG,
                                             scale);
    }

    // 5. causal softmax in place (+ zero-fill diagonal-band slack)
    {
        dim3 grid(S, HQ);
        softmax_kernel<<<grid, 256>>>(scores);
    }

    // 6. attn[:, h*128:(h+1)*128] = P_h @ V_{h/4}   (causal K-limit)
    {
        dim3 grid(HD / BNN, S / BMM, HQ);
        sgemm_kernel<false, 2><<<grid, 256>>>(scores, qkv + D + G * HD, attn,
                                              S, HD, S, S, E, D,
                                              (long long)S * S, HD, HD, HG,
                                              1.0f);
    }

    // 7. out = attn @ w_out^T
    {
        dim3 grid(D / BNN, S / BMM, 1);
        sgemm_kernel<true, 0><<<grid, 256>>>(attn, w_out, out,
                                             S, D, D, D, D, D,
                                             0, 0, 0, 1, 1.0f);
    }
}

// round 6
// speedup vs baseline: 1.6575x; 1.6575x over previous
#include <cuda_runtime.h>
#include <cuda_bf16.h>
#include <math.h>
#include <float.h>
#include <stdint.h>

// Problem constants
#define S    2048
#define D    4096         // H*HD
#define HQ   32           // query heads
#define G    8            // kv heads
#define HD   128
#define E    6144         // D + 2*G*HD
#define HG   4            // HQ / G
#define EPSF 1e-5f

typedef __nv_bfloat16 bf16;

// ---------------------------------------------------------------------------
// Scratch (device globals; no runtime allocation allowed)
// ---------------------------------------------------------------------------
__device__ float g_qkv[(size_t)S * E];
__device__ float g_scores[(size_t)HQ * S * S];
__device__ float g_attn[(size_t)S * D];
__device__ float g_cos[(size_t)S * (HD / 2)];
__device__ float g_sin[(size_t)S * (HD / 2)];

__device__ bf16 g_xh[(size_t)S * D],        g_xl[(size_t)S * D];
__device__ bf16 g_wqh[(size_t)E * D],       g_wql[(size_t)E * D];
__device__ bf16 g_woh[(size_t)D * D],       g_wol[(size_t)D * D];
__device__ bf16 g_qh[(size_t)S * D],        g_ql[(size_t)S * D];
__device__ bf16 g_kh[(size_t)S * G * HD],   g_kl[(size_t)S * G * HD];
__device__ bf16 g_vth[(size_t)G * HD * S],  g_vtl[(size_t)G * HD * S];
__device__ bf16 g_ph[(size_t)HQ * S * S],   g_pl[(size_t)HQ * S * S];
__device__ bf16 g_ah[(size_t)S * D],        g_al[(size_t)S * D];

// ---------------------------------------------------------------------------
// Helpers
// ---------------------------------------------------------------------------
__device__ __forceinline__ uint32_t smem_u32_of(const void* p) {
    uint32_t a;
    asm("{ .reg .u64 t; cvta.to.shared.u64 t, %1; cvt.u32.u64 %0, t; }" : "=r"(a) : "l"(p));
    return a;
}

#define CP_ASYNC16(dst, src) \
    asm volatile("cp.async.cg.shared.global [%0], [%1], 16;" :: "r"(dst), "l"(src))
#define CP_COMMIT()  asm volatile("cp.async.commit_group;" ::: "memory")

#define LDMAT_X4(r0, r1, r2, r3, a) \
    asm volatile("ldmatrix.sync.aligned.m8n8.x4.shared.b16 {%0,%1,%2,%3}, [%4];" \
        : "=r"(r0), "=r"(r1), "=r"(r2), "=r"(r3) : "r"(a))

#define MMA16816(d, a, b0v, b1v) \
    asm volatile("mma.sync.aligned.m16n8k16.row.col.f32.bf16.bf16.f32 " \
        "{%0,%1,%2,%3}, {%4,%5,%6,%7}, {%8,%9}, {%0,%1,%2,%3};" \
        : "+f"((d)[0]), "+f"((d)[1]), "+f"((d)[2]), "+f"((d)[3]) \
        : "r"((a)[0]), "r"((a)[1]), "r"((a)[2]), "r"((a)[3]), "r"(b0v), "r"(b1v))

// ---------------------------------------------------------------------------
// Warp-MMA bf16x3 GEMM:  C[M,N] = alpha * A[M,K] * B[N,K]^T   (fp32 in/out)
// A,B as bf16 hi/lo pairs; extended K via planes: Ah*Bh, Al*Bh, Ah*Bl.
// Block tile 128x128x32, 256 thr (8 warps, 2x4), warp tile 64x32.
// 2-stage cp.async smem pipeline; 80B smem row stride (conflict-free ldmatrix).
// NOTE: B is stored [n][k] with k contiguous; for mma.row.col the B fragment
// comes from ldmatrix WITHOUT .trans (non-trans of [n][k] == k-major fragment).
//   CAUSAL 0: none
//   CAUSAL 1: skip tile if n0 >= m0+128   (QK^T)
//   CAUSAL 2: K limited to min(K, m0+128) (P@V)
// Per-z offsets; B z-index = z / bzdiv (GQA).
// ---------------------------------------------------------------------------
#define RS   80                      // smem row stride bytes (32 bf16 + 16B pad)
#define TILE_B (128 * RS)            // 10240 bytes per operand tile
#define STAGE_B (2 * TILE_B)         // A + B per stage

__device__ __forceinline__ void load_tile_async(uint32_t sdst, const bf16* src,
                                                int ld, int tid) {
    #pragma unroll
    for (int it = 0; it < 2; it++) {
        int idx = tid + it * 256;
        int row = idx >> 2, ch = idx & 3;
        const bf16* g = src + (long long)row * ld + ch * 8;
        CP_ASYNC16(sdst + row * RS + ch * 16, g);
    }
}

template <int CAUSAL>
__global__ void __launch_bounds__(256, 1)
mma_gemm(const bf16* __restrict__ Ah, const bf16* __restrict__ Al,
         const bf16* __restrict__ Bh, const bf16* __restrict__ Bl,
         float* __restrict__ C, int K, int lda, int ldb, int ldc,
         long long sAz, long long sBz, long long sCz, int bzdiv, float alpha) {
    int m0 = blockIdx.y * 128;
    int n0 = blockIdx.x * 128;
    if (CAUSAL == 1 && n0 >= m0 + 128) return;

    int z = blockIdx.z;
    const bf16* AhZ = Ah + (long long)z * sAz;
    const bf16* AlZ = Al + (long long)z * sAz;
    const bf16* BhZ = Bh + (long long)(z / bzdiv) * sBz;
    const bf16* BlZ = Bl + (long long)(z / bzdiv) * sBz;
    float*      Cz  = C  + (long long)z * sCz;

    int Keff   = (CAUSAL == 2) ? ((K < m0 + 128) ? K : (m0 + 128)) : K;
    int ktiles = Keff >> 5;          // K-tiles of 32
    int NT     = 3 * ktiles;

    __shared__ __align__(16) char smem[2 * STAGE_B];   // 40 KB
    uint32_t smb = smem_u32_of(smem);

    int tid  = threadIdx.x;
    int warp = tid >> 5, lane = tid & 31;
    int wm = (warp >> 2) * 64;       // warp row offset (2 warps in m)
    int wn = (warp & 3) * 32;        // warp col offset (4 warps in n)

    float acc[4][4][4];
    #pragma unroll
    for (int i = 0; i < 4; i++)
        #pragma unroll
        for (int j = 0; j < 4; j++)
            #pragma unroll
            for (int t = 0; t < 4; t++) acc[i][j][t] = 0.0f;

    // per-lane ldmatrix base offsets (within a stage)
    // A: tiles (m0-7,k0-7),(m8-15,k0-7),(m0-7,k8-15),(m8-15,k8-15)
    uint32_t aLane = (uint32_t)((wm + (lane & 15)) * RS + (lane >> 4) * 16);
    // B: tiles (n0-7,k0-7),(n0-7,k8-15),(n8-15,k0-7),(n8-15,k8-15)
    uint32_t bLane = (uint32_t)((wn + ((lane >> 4) << 3) + (lane & 7)) * RS
                                + ((lane >> 3) & 1) * 16);

    // iteration i -> plane p = i / ktiles, k-chunk kc = i % ktiles
    auto srcA = [&](int i) -> const bf16* {
        int p = i / ktiles, kc = i - p * ktiles;
        const bf16* Ap = (p == 1) ? AlZ : AhZ;
        return Ap + (long long)m0 * lda + kc * 32;
    };
    auto srcB = [&](int i) -> const bf16* {
        int p = i / ktiles, kc = i - p * ktiles;
        const bf16* Bp = (p == 2) ? BlZ : BhZ;
        return Bp + (long long)n0 * ldb + kc * 32;
    };

    // prologue
    load_tile_async(smb, srcA(0), lda, tid);
    load_tile_async(smb + TILE_B, srcB(0), ldb, tid);
    CP_COMMIT();

    for (int i = 0; i < NT; i++) {
        int st = i & 1;
        if (i + 1 < NT) {
            uint32_t nb = smb + ((i + 1) & 1) * STAGE_B;
            load_tile_async(nb, srcA(i + 1), lda, tid);
            load_tile_async(nb + TILE_B, srcB(i + 1), ldb, tid);
            CP_COMMIT();
            asm volatile("cp.async.wait_group 1;" ::: "memory");
        } else {
            asm volatile("cp.async.wait_group 0;" ::: "memory");
        }
        __syncthreads();

        uint32_t sA = smb + st * STAGE_B;
        uint32_t sB = sA + TILE_B;
        uint32_t aAddr = sA + aLane;
        uint32_t bAddr = sB + bLane;

        #pragma unroll
        for (int kk = 0; kk < 2; kk++) {           // two k16 steps per tile
            uint32_t a[4][4], bb[2][4];
            #pragma unroll
            for (int ma = 0; ma < 4; ma++)
                LDMAT_X4(a[ma][0], a[ma][1], a[ma][2], a[ma][3],
                         aAddr + ma * (16 * RS) + kk * 32);
            #pragma unroll
            for (int nb2 = 0; nb2 < 2; nb2++)
                LDMAT_X4(bb[nb2][0], bb[nb2][1], bb[nb2][2], bb[nb2][3],
                         bAddr + nb2 * (16 * RS) + kk * 32);
            #pragma unroll
            for (int ma = 0; ma < 4; ma++)
                #pragma unroll
                for (int nb2 = 0; nb2 < 2; nb2++) {
                    MMA16816(acc[ma][nb2 * 2 + 0], a[ma], bb[nb2][0], bb[nb2][1]);
                    MMA16816(acc[ma][nb2 * 2 + 1], a[ma], bb[nb2][2], bb[nb2][3]);
                }
        }
        __syncthreads();
    }

    // epilogue
    int group = lane >> 2, tig = lane & 3;
    #pragma unroll
    for (int ma = 0; ma < 4; ma++) {
        int r0 = m0 + wm + ma * 16 + group;
        #pragma unroll
        for (int na = 0; na < 4; na++) {
            int c = n0 + wn + na * 8 + tig * 2;
            float2 v0 = make_float2(acc[ma][na][0] * alpha, acc[ma][na][1] * alpha);
            float2 v1 = make_float2(acc[ma][na][2] * alpha, acc[ma][na][3] * alpha);
            *(float2*)(Cz + (long long)r0 * ldc + c)       = v0;
            *(float2*)(Cz + (long long)(r0 + 8) * ldc + c) = v1;
        }
    }
}

// ---------------------------------------------------------------------------
// fp32 -> bf16 hi/lo split (2D strided source, contiguous dest)
// ---------------------------------------------------------------------------
__global__ void split_kernel(const float* __restrict__ src, int ldsrc, int cols,
                             bf16* __restrict__ hi, bf16* __restrict__ lo,
                             long long total) {
    long long i4 = ((long long)blockIdx.x * blockDim.x + threadIdx.x) * 4;
    if (i4 >= total) return;
    long long r = i4 / cols;
    int c = (int)(i4 - r * cols);
    float4 v = *(const float4*)(src + r * (long long)ldsrc + c);
    bf16 h0 = __float2bfloat16(v.x), h1 = __float2bfloat16(v.y);
    bf16 h2 = __float2bfloat16(v.z), h3 = __float2bfloat16(v.w);
    bf16 l0 = __float2bfloat16(v.x - __bfloat162float(h0));
    bf16 l1 = __float2bfloat16(v.y - __bfloat162float(h1));
    bf16 l2 = __float2bfloat16(v.z - __bfloat162float(h2));
    bf16 l3 = __float2bfloat16(v.w - __bfloat162float(h3));
    *(__nv_bfloat162*)(hi + i4)     = __nv_bfloat162(h0, h1);
    *(__nv_bfloat162*)(hi + i4 + 2) = __nv_bfloat162(h2, h3);
    *(__nv_bfloat162*)(lo + i4)     = __nv_bfloat162(l0, l1);
    *(__nv_bfloat162*)(lo + i4 + 2) = __nv_bfloat162(l2, l3);
}

// V transpose + split: vt[g][d][t] = split(qkv[t, D + G*HD + g*HD + d])
__global__ void vsplit_kernel(const float* __restrict__ qkv,
                              bf16* __restrict__ vth, bf16* __restrict__ vtl) {
    int t = blockIdx.x, g = blockIdx.y, d = threadIdx.x;
    float v = qkv[(long long)t * E + D + G * HD + g * HD + d];
    bf16 h = __float2bfloat16(v);
    bf16 l = __float2bfloat16(v - __bfloat162float(h));
    long long o = ((long long)(g * HD + d)) * S + t;
    vth[o] = h; vtl[o] = l;
}

// ---------------------------------------------------------------------------
// RoPE cos/sin table (matches reference fp32 semantics)
// ---------------------------------------------------------------------------
__global__ void rope_table_kernel(float* __restrict__ cosT, float* __restrict__ sinT) {
    int idx = blockIdx.x * blockDim.x + threadIdx.x;
    if (idx >= S * (HD / 2)) return;
    int s = idx >> 6;
    int i = idx & 63;
    double freq_d = pow(1.0e6, -(double)(2 * i) / 128.0);
    float  ang = (float)s * (float)freq_d;
    double cd, sd;
    sincos((double)ang, &sd, &cd);
    cosT[idx] = (float)cd;
    sinT[idx] = (float)sd;
}

// ---------------------------------------------------------------------------
// Fused RMSNorm + RoPE, in place on q/k inside g_qkv. One warp per row.
// ---------------------------------------------------------------------------
__global__ void rmsnorm_rope_kernel(float* __restrict__ qkv,
                                    const float* __restrict__ qw,
                                    const float* __restrict__ kw,
                                    const float* __restrict__ cosT,
                                    const float* __restrict__ sinT) {
    int gwarp = (blockIdx.x * blockDim.x + threadIdx.x) >> 5;
    int lane  = threadIdx.x & 31;
    const int NROWS = S * (HQ + G);
    if (gwarp >= NROWS) return;
    int s  = gwarp / (HQ + G);
    int hh = gwarp % (HQ + G);

    float* row;
    const float* w;
    if (hh < HQ) { row = qkv + (long long)s * E + hh * HD;            w = qw; }
    else         { row = qkv + (long long)s * E + D + (hh - HQ) * HD; w = kw; }

    float2* row2 = (float2*)row;
    float2 a = row2[lane], b = row2[lane + 32];
    float ss = a.x * a.x + a.y * a.y + b.x * b.x + b.y * b.y;
    #pragma unroll
    for (int o = 16; o; o >>= 1) ss += __shfl_xor_sync(0xFFFFFFFFu, ss, o);
    float r = rsqrtf(ss * (1.0f / 128.0f) + EPSF);

    const float2* w2 = (const float2*)w;
    float2 wa = w2[lane], wb = w2[lane + 32];
    float ax = (a.x * r) * wa.x, ay = (a.y * r) * wa.y;
    float bx = (b.x * r) * wb.x, by = (b.y * r) * wb.y;

    int base = s * (HD / 2);
    float c0 = cosT[base + lane],      s0 = sinT[base + lane];
    float c1 = cosT[base + lane + 32], s1 = sinT[base + lane + 32];
    row2[lane]      = make_float2(ax * c0 - ay * s0, ax * s0 + ay * c0);
    row2[lane + 32] = make_float2(bx * c1 - by * s1, bx * s1 + by * c1);
}

// ---------------------------------------------------------------------------
// Causal softmax reading fp32 scores, writing bf16 hi/lo probs.
// Zero-fills up to ceil128(s+1) (exactly the slack the K-limited PV reads).
// ---------------------------------------------------------------------------
__global__ void softmax_split_kernel(const float* __restrict__ scores,
                                     bf16* __restrict__ ph, bf16* __restrict__ pl) {
    int s = blockIdx.x, h = blockIdx.y;
    const float* row = scores + ((long long)h * S + s) * (long long)S;
    bf16* phr = ph + ((long long)h * S + s) * (long long)S;
    bf16* plr = pl + ((long long)h * S + s) * (long long)S;
    int n = s + 1;
    int nend = (n + 127) & ~127;
    int tid = threadIdx.x;

    float v[8];
    float mx = -FLT_MAX;
    #pragma unroll
    for (int i = 0; i < 8; i++) {
        int t = tid + i * 256;
        v[i] = (t < n) ? row[t] : -FLT_MAX;
        mx = fmaxf(mx, v[i]);
    }
    __shared__ float red[8];
    #pragma unroll
    for (int o = 16; o; o >>= 1) mx = fmaxf(mx, __shfl_xor_sync(0xFFFFFFFFu, mx, o));
    if ((tid & 31) == 0) red[tid >> 5] = mx;
    __syncthreads();
    mx = red[0];
    #pragma unroll
    for (int w = 1; w < 8; w++) mx = fmaxf(mx, red[w]);
    __syncthreads();

    float sum = 0.0f;
    #pragma unroll
    for (int i = 0; i < 8; i++) {
        int t = tid + i * 256;
        v[i] = (t < n) ? expf(v[i] - mx) : 0.0f;
        sum += v[i];
    }
    #pragma unroll
    for (int o = 16; o; o >>= 1) sum += __shfl_xor_sync(0xFFFFFFFFu, sum, o);
    if ((tid & 31) == 0) red[tid >> 5] = sum;
    __syncthreads();
    float tot = red[0];
    #pragma unroll
    for (int w = 1; w < 8; w++) tot += red[w];
    float inv = 1.0f / tot;

    #pragma unroll
    for (int i = 0; i < 8; i++) {
        int t = tid + i * 256;
        if (t < nend) {
            float pv = (t < n) ? v[i] * inv : 0.0f;
            bf16 hh = __float2bfloat16(pv);
            bf16 ll = __float2bfloat16(pv - __bfloat162float(hh));
            phr[t] = hh; plr[t] = ll;
        }
    }
}

// ---------------------------------------------------------------------------
// Launch
// ---------------------------------------------------------------------------
extern "C" void kernel_launch(void* const* d_in, const int* in_sizes, int n_in,
                              void* d_out, int out_size) {
    const float* x     = (const float*)d_in[0];
    const float* w_qkv = (const float*)d_in[1];
    const float* w_out = (const float*)d_in[2];
    const float* qw    = (const float*)d_in[3];
    const float* kw    = (const float*)d_in[4];
    float* out = (float*)d_out;

    float *qkv, *scores, *attn, *cosT, *sinT;
    cudaGetSymbolAddress((void**)&qkv,    g_qkv);
    cudaGetSymbolAddress((void**)&scores, g_scores);
    cudaGetSymbolAddress((void**)&attn,   g_attn);
    cudaGetSymbolAddress((void**)&cosT,   g_cos);
    cudaGetSymbolAddress((void**)&sinT,   g_sin);
    bf16 *xh,*xl,*wqh,*wql,*woh,*wol,*qh,*ql,*kh,*kl,*vth,*vtl,*ph,*pl,*ah,*al;
    cudaGetSymbolAddress((void**)&xh,  g_xh);  cudaGetSymbolAddress((void**)&xl,  g_xl);
    cudaGetSymbolAddress((void**)&wqh, g_wqh); cudaGetSymbolAddress((void**)&wql, g_wql);
    cudaGetSymbolAddress((void**)&woh, g_woh); cudaGetSymbolAddress((void**)&wol, g_wol);
    cudaGetSymbolAddress((void**)&qh,  g_qh);  cudaGetSymbolAddress((void**)&ql,  g_ql);
    cudaGetSymbolAddress((void**)&kh,  g_kh);  cudaGetSymbolAddress((void**)&kl,  g_kl);
    cudaGetSymbolAddress((void**)&vth, g_vth); cudaGetSymbolAddress((void**)&vtl, g_vtl);
    cudaGetSymbolAddress((void**)&ph,  g_ph);  cudaGetSymbolAddress((void**)&pl,  g_pl);
    cudaGetSymbolAddress((void**)&ah,  g_ah);  cudaGetSymbolAddress((void**)&al,  g_al);

    const float scale = 0.08838834764831845f;   // 1/sqrt(128)

    // 1. RoPE tables
    rope_table_kernel<<<(S * (HD / 2) + 255) / 256, 256>>>(cosT, sinT);

    // 2. Splits for QKV GEMM inputs (and out-proj weights)
    {
        long long tx = (long long)S * D;
        split_kernel<<<(unsigned)((tx / 4 + 255) / 256), 256>>>(x, D, D, xh, xl, tx);
        long long tw = (long long)E * D;
        split_kernel<<<(unsigned)((tw / 4 + 255) / 256), 256>>>(w_qkv, D, D, wqh, wql, tw);
        long long to = (long long)D * D;
        split_kernel<<<(unsigned)((to / 4 + 255) / 256), 256>>>(w_out, D, D, woh, wol, to);
    }

    // 3. QKV projection: qkv = x @ w_qkv^T
    {
        dim3 grid(E / 128, S / 128, 1);
        mma_gemm<0><<<grid, 256>>>(xh, xl, wqh, wql, qkv,
                                   D, D, D, E, 0, 0, 0, 1, 1.0f);
    }

    // 4. RMSNorm + RoPE in place
    rmsnorm_rope_kernel<<<S * (HQ + G) / 8, 256>>>(qkv, qw, kw, cosT, sinT);

    // 5. Split q, k; transpose+split v
    {
        long long tq = (long long)S * D;
        split_kernel<<<(unsigned)((tq / 4 + 255) / 256), 256>>>(qkv, E, D, qh, ql, tq);
        long long tk = (long long)S * G * HD;
        split_kernel<<<(unsigned)((tk / 4 + 255) / 256), 256>>>(qkv + D, E, G * HD, kh, kl, tk);
        dim3 vg(S, G);
        vsplit_kernel<<<vg, HD>>>(qkv, vth, vtl);
    }

    // 6. scores[h] = scale * Q_h @ K_{h/4}^T   (causal tile skip)
    {
        dim3 grid(S / 128, S / 128, HQ);
        mma_gemm<1><<<grid, 256>>>(qh, ql, kh, kl, scores,
                                   HD, D, G * HD, S,
                                   HD, HD, (long long)S * S, HG, scale);
    }

    // 7. causal softmax -> bf16 hi/lo probs
    {
        dim3 grid(S, HQ);
        softmax_split_kernel<<<grid, 256>>>(scores, ph, pl);
    }

    // 8. attn[:, h*128:(h+1)*128] = P_h @ V_{h/4}^T   (K-limited)
    {
        dim3 grid(1, S / 128, HQ);
        mma_gemm<2><<<grid, 256>>>(ph, pl, vth, vtl, attn,
                                   S, S, S, D,
                                   (long long)S * S, (long long)HD * S, HD, HG, 1.0f);
    }

    // 9. split attn, out = attn @ w_out^T
    {
        long long ta = (long long)S * D;
        split_kernel<<<(unsigned)((ta / 4 + 255) / 256), 256>>>(attn, D, D, ah, al, ta);
        dim3 grid(D / 128, S / 128, 1);
        mma_gemm<0><<<grid, 256>>>(ah, al, woh, wol, out,
                                   D, D, D, D, 0, 0, 0, 1, 1.0f);
    }
}

// round 8
// speedup vs baseline: 2.7039x; 1.6313x over previous
#include <cuda_runtime.h>
#include <cuda_bf16.h>
#include <math.h>
#include <float.h>
#include <stdint.h>

// Problem constants
#define S    2048
#define D    4096         // H*HD
#define HQ   32           // query heads
#define G    8            // kv heads
#define HD   128
#define E    6144         // D + 2*G*HD
#define HG   4            // HQ / G
#define EPSF 1e-5f

typedef __nv_bfloat16 bf16;
typedef __nv_bfloat162 bf162;

// ---------------------------------------------------------------------------
// Scratch (device globals; no runtime allocation allowed)
// ---------------------------------------------------------------------------
__device__ float g_qkv[(size_t)S * E];
__device__ float g_scores[(size_t)HQ * S * S];
__device__ float g_cos[(size_t)S * (HD / 2)];
__device__ float g_sin[(size_t)S * (HD / 2)];

__device__ bf16 g_xh[(size_t)S * D],        g_xl[(size_t)S * D];
__device__ bf16 g_wqh[(size_t)E * D],       g_wql[(size_t)E * D];
__device__ bf16 g_woh[(size_t)D * D],       g_wol[(size_t)D * D];
__device__ bf16 g_qh[(size_t)S * D],        g_ql[(size_t)S * D];
__device__ bf16 g_kh[(size_t)S * G * HD],   g_kl[(size_t)S * G * HD];
__device__ bf16 g_vth[(size_t)G * HD * S],  g_vtl[(size_t)G * HD * S];
__device__ bf16 g_ph[(size_t)HQ * S * S],   g_pl[(size_t)HQ * S * S];
__device__ bf16 g_ah[(size_t)S * D],        g_al[(size_t)S * D];

// ---------------------------------------------------------------------------
// Helpers
// ---------------------------------------------------------------------------
__device__ __forceinline__ uint32_t smem_u32_of(const void* p) {
    uint32_t a;
    asm("{ .reg .u64 t; cvta.to.shared.u64 t, %1; cvt.u32.u64 %0, t; }" : "=r"(a) : "l"(p));
    return a;
}

#define CP_ASYNC16(dst, src) \
    asm volatile("cp.async.cg.shared.global [%0], [%1], 16;" :: "r"(dst), "l"(src))
#define CP_COMMIT()  asm volatile("cp.async.commit_group;" ::: "memory")

#define LDMAT_X4(r0, r1, r2, r3, a) \
    asm volatile("ldmatrix.sync.aligned.m8n8.x4.shared.b16 {%0,%1,%2,%3}, [%4];" \
        : "=r"(r0), "=r"(r1), "=r"(r2), "=r"(r3) : "r"(a))

#define MMA16816(d, a, b0v, b1v) \
    asm volatile("mma.sync.aligned.m16n8k16.row.col.f32.bf16.bf16.f32 " \
        "{%0,%1,%2,%3}, {%4,%5,%6,%7}, {%8,%9}, {%0,%1,%2,%3};" \
        : "+f"((d)[0]), "+f"((d)[1]), "+f"((d)[2]), "+f"((d)[3]) \
        : "r"((a)[0]), "r"((a)[1]), "r"((a)[2]), "r"((a)[3]), "r"(b0v), "r"(b1v))

__device__ __forceinline__ void split1(float v, bf16& h, bf16& l) {
    h = __float2bfloat16(v);
    l = __float2bfloat16(v - __bfloat162float(h));
}

// ---------------------------------------------------------------------------
// Warp-MMA bf16x3 GEMM:  C[M,N] = alpha * A[M,K] * B[N,K]^T   (fp32 accum)
// A,B as bf16 hi/lo pairs; extended K via planes: Ah*Bh, Al*Bh, Ah*Bl.
// Block tile 128x128x32, 256 thr (8 warps, 2x4), warp tile 64x32.
// 3-stage cp.async pipeline, ONE __syncthreads per K-iteration.
// 80B smem row stride (conflict-free ldmatrix, non-trans for [n][k] B).
//   CAUSAL 0: none | 1: skip tile if n0>=m0+128 (QK) | 2: K<=m0+128 (PV)
//   SPLITOUT 0: fp32 C | 1: bf16 hi/lo C pair
// Per-z offsets; B z-index = z / bzdiv (GQA).
// ---------------------------------------------------------------------------
#define RS      80                   // smem row stride bytes (32 bf16 + 16B pad)
#define TILE_B  (128 * RS)           // 10240 bytes per operand tile
#define STAGE_B (2 * TILE_B)         // A + B per stage
#define NSTG    3

__device__ __forceinline__ void load_tile_async(uint32_t sdst, const bf16* src,
                                                int ld, int tid) {
    #pragma unroll
    for (int it = 0; it < 2; it++) {
        int idx = tid + it * 256;
        int row = idx >> 2, ch = idx & 3;
        const bf16* g = src + (long long)row * ld + ch * 8;
        CP_ASYNC16(sdst + row * RS + ch * 16, g);
    }
}

template <int CAUSAL, int SPLITOUT>
__global__ void __launch_bounds__(256, 2)
mma_gemm(const bf16* __restrict__ Ah, const bf16* __restrict__ Al,
         const bf16* __restrict__ Bh, const bf16* __restrict__ Bl,
         float* __restrict__ C, bf16* __restrict__ Ch, bf16* __restrict__ Cl,
         int K, int lda, int ldb, int ldc,
         long long sAz, long long sBz, long long sCz, int bzdiv, float alpha) {
    int m0 = blockIdx.y * 128;
    int n0 = blockIdx.x * 128;
    if (CAUSAL == 1 && n0 >= m0 + 128) return;

    int z = blockIdx.z;
    const bf16* AhZ = Ah + (long long)z * sAz;
    const bf16* AlZ = Al + (long long)z * sAz;
    const bf16* BhZ = Bh + (long long)(z / bzdiv) * sBz;
    const bf16* BlZ = Bl + (long long)(z / bzdiv) * sBz;

    int Keff   = (CAUSAL == 2) ? ((K < m0 + 128) ? K : (m0 + 128)) : K;
    int ktiles = Keff >> 5;          // K-tiles of 32
    int NT     = 3 * ktiles;

    extern __shared__ __align__(16) char smem[];     // NSTG * STAGE_B
    uint32_t smb = smem_u32_of(smem);

    int tid  = threadIdx.x;
    int warp = tid >> 5, lane = tid & 31;
    int wm = (warp >> 2) * 64;       // warp row offset (2 warps in m)
    int wn = (warp & 3) * 32;        // warp col offset (4 warps in n)

    float acc[4][4][4];
    #pragma unroll
    for (int i = 0; i < 4; i++)
        #pragma unroll
        for (int j = 0; j < 4; j++)
            #pragma unroll
            for (int t = 0; t < 4; t++) acc[i][j][t] = 0.0f;

    // per-lane ldmatrix base offsets (within a stage)
    uint32_t aLane = (uint32_t)((wm + (lane & 15)) * RS + (lane >> 4) * 16);
    uint32_t bLane = (uint32_t)((wn + ((lane >> 4) << 3) + (lane & 7)) * RS
                                + ((lane >> 3) & 1) * 16);

    // iteration i -> plane p = i / ktiles, k-chunk kc = i % ktiles
    auto srcA = [&](int i) -> const bf16* {
        int p = i / ktiles, kc = i - p * ktiles;
        const bf16* Ap = (p == 1) ? AlZ : AhZ;
        return Ap + (long long)m0 * lda + kc * 32;
    };
    auto srcB = [&](int i) -> const bf16* {
        int p = i / ktiles, kc = i - p * ktiles;
        const bf16* Bp = (p == 2) ? BlZ : BhZ;
        return Bp + (long long)n0 * ldb + kc * 32;
    };

    // prologue: issue stages 0..NSTG-2
    #pragma unroll
    for (int s = 0; s < NSTG - 1; s++) {
        uint32_t sb = smb + s * STAGE_B;
        load_tile_async(sb, srcA(s), lda, tid);
        load_tile_async(sb + TILE_B, srcB(s), ldb, tid);
        CP_COMMIT();
    }

    for (int i = 0; i < NT; i++) {
        // stage i ready when at most (groups committed after i) remain pending
        if (i == NT - 1) asm volatile("cp.async.wait_group 0;" ::: "memory");
        else             asm volatile("cp.async.wait_group 1;" ::: "memory");
        __syncthreads();

        // issue loads for stage i+NSTG-1 into slot (i-1)%NSTG (freed by the sync)
        if (i + NSTG - 1 < NT) {
            uint32_t nb = smb + ((i + NSTG - 1) % NSTG) * STAGE_B;
            load_tile_async(nb, srcA(i + NSTG - 1), lda, tid);
            load_tile_async(nb + TILE_B, srcB(i + NSTG - 1), ldb, tid);
            CP_COMMIT();
        }

        uint32_t sA = smb + (i % NSTG) * STAGE_B;
        uint32_t sB = sA + TILE_B;
        uint32_t aAddr = sA + aLane;
        uint32_t bAddr = sB + bLane;

        #pragma unroll
        for (int kk = 0; kk < 2; kk++) {           // two k16 steps per tile
            uint32_t a[4][4], bb[2][4];
            #pragma unroll
            for (int ma = 0; ma < 4; ma++)
                LDMAT_X4(a[ma][0], a[ma][1], a[ma][2], a[ma][3],
                         aAddr + ma * (16 * RS) + kk * 32);
            #pragma unroll
            for (int nb2 = 0; nb2 < 2; nb2++)
                LDMAT_X4(bb[nb2][0], bb[nb2][1], bb[nb2][2], bb[nb2][3],
                         bAddr + nb2 * (16 * RS) + kk * 32);
            #pragma unroll
            for (int ma = 0; ma < 4; ma++)
                #pragma unroll
                for (int nb2 = 0; nb2 < 2; nb2++) {
                    MMA16816(acc[ma][nb2 * 2 + 0], a[ma], bb[nb2][0], bb[nb2][1]);
                    MMA16816(acc[ma][nb2 * 2 + 1], a[ma], bb[nb2][2], bb[nb2][3]);
                }
        }
    }

    // epilogue
    int group = lane >> 2, tig = lane & 3;
    #pragma unroll
    for (int ma = 0; ma < 4; ma++) {
        int r0 = m0 + wm + ma * 16 + group;
        #pragma unroll
        for (int na = 0; na < 4; na++) {
            int c = n0 + wn + na * 8 + tig * 2;
            #pragma unroll
            for (int half = 0; half < 2; half++) {
                long long off = (long long)(r0 + half * 8) * ldc + c
                              + (long long)z * sCz;
                float v0 = acc[ma][na][half * 2 + 0] * alpha;
                float v1 = acc[ma][na][half * 2 + 1] * alpha;
                if (SPLITOUT) {
                    bf16 h0, l0, h1, l1;
                    split1(v0, h0, l0); split1(v1, h1, l1);
                    *(bf162*)(Ch + off) = bf162(h0, h1);
                    *(bf162*)(Cl + off) = bf162(l0, l1);
                } else {
                    *(float2*)(C + off) = make_float2(v0, v1);
                }
            }
        }
    }
}

// ---------------------------------------------------------------------------
// fp32 -> bf16 hi/lo split (2D strided source, contiguous dest)
// ---------------------------------------------------------------------------
__global__ void split_kernel(const float* __restrict__ src, int ldsrc, int cols,
                             bf16* __restrict__ hi, bf16* __restrict__ lo,
                             long long total) {
    long long i4 = ((long long)blockIdx.x * blockDim.x + threadIdx.x) * 4;
    if (i4 >= total) return;
    long long r = i4 / cols;
    int c = (int)(i4 - r * cols);
    float4 v = *(const float4*)(src + r * (long long)ldsrc + c);
    bf16 h0, l0, h1, l1, h2, l2, h3, l3;
    split1(v.x, h0, l0); split1(v.y, h1, l1);
    split1(v.z, h2, l2); split1(v.w, h3, l3);
    *(bf162*)(hi + i4)     = bf162(h0, h1);
    *(bf162*)(hi + i4 + 2) = bf162(h2, h3);
    *(bf162*)(lo + i4)     = bf162(l0, l1);
    *(bf162*)(lo + i4 + 2) = bf162(l2, l3);
}

// V transpose + split: vt[g][d][t] = split(qkv[t, D + G*HD + g*HD + d])
__global__ void vsplit_kernel(const float* __restrict__ qkv,
                              bf16* __restrict__ vth, bf16* __restrict__ vtl) {
    int t = blockIdx.x, g = blockIdx.y, d = threadIdx.x;
    float v = qkv[(long long)t * E + D + G * HD + g * HD + d];
    bf16 h, l;
    split1(v, h, l);
    long long o = ((long long)(g * HD + d)) * S + t;
    vth[o] = h; vtl[o] = l;
}

// ---------------------------------------------------------------------------
// RoPE cos/sin table (matches reference fp32 semantics)
// ---------------------------------------------------------------------------
__global__ void rope_table_kernel(float* __restrict__ cosT, float* __restrict__ sinT) {
    int idx = blockIdx.x * blockDim.x + threadIdx.x;
    if (idx >= S * (HD / 2)) return;
    int s = idx >> 6;
    int i = idx & 63;
    double freq_d = pow(1.0e6, -(double)(2 * i) / 128.0);
    float  ang = (float)s * (float)freq_d;
    double cd, sd;
    sincos((double)ang, &sd, &cd);
    cosT[idx] = (float)cd;
    sinT[idx] = (float)sd;
}

// ---------------------------------------------------------------------------
// Fused RMSNorm + RoPE + bf16 hi/lo split. Reads fp32 q/k from g_qkv,
// writes qh/ql (dense [S,D]) and kh/kl (dense [S,G*HD]). One warp per row.
// ---------------------------------------------------------------------------
__global__ void rmsnorm_rope_split_kernel(const float* __restrict__ qkv,
                                          const float* __restrict__ qw,
                                          const float* __restrict__ kw,
                                          const float* __restrict__ cosT,
                                          const float* __restrict__ sinT,
                                          bf16* __restrict__ qh, bf16* __restrict__ ql,
                                          bf16* __restrict__ kh, bf16* __restrict__ kl) {
    int gwarp = (blockIdx.x * blockDim.x + threadIdx.x) >> 5;
    int lane  = threadIdx.x & 31;
    const int NROWS = S * (HQ + G);
    if (gwarp >= NROWS) return;
    int s  = gwarp / (HQ + G);
    int hh = gwarp % (HQ + G);

    const float* row;
    const float* w;
    bf16 *dh, *dl;
    if (hh < HQ) {
        row = qkv + (long long)s * E + hh * HD;            w = qw;
        dh = qh + (long long)s * D + hh * HD;
        dl = ql + (long long)s * D + hh * HD;
    } else {
        row = qkv + (long long)s * E + D + (hh - HQ) * HD; w = kw;
        dh = kh + (long long)s * (G * HD) + (hh - HQ) * HD;
        dl = kl + (long long)s * (G * HD) + (hh - HQ) * HD;
    }

    const float2* row2 = (const float2*)row;
    float2 a = row2[lane], b = row2[lane + 32];
    float ss = a.x * a.x + a.y * a.y + b.x * b.x + b.y * b.y;
    #pragma unroll
    for (int o = 16; o; o >>= 1) ss += __shfl_xor_sync(0xFFFFFFFFu, ss, o);
    float r = rsqrtf(ss * (1.0f / 128.0f) + EPSF);

    const float2* w2 = (const float2*)w;
    float2 wa = w2[lane], wb = w2[lane + 32];
    float ax = (a.x * r) * wa.x, ay = (a.y * r) * wa.y;
    float bx = (b.x * r) * wb.x, by = (b.y * r) * wb.y;

    int base = s * (HD / 2);
    float c0 = cosT[base + lane],      s0 = sinT[base + lane];
    float c1 = cosT[base + lane + 32], s1 = sinT[base + lane + 32];

    float o0 = ax * c0 - ay * s0, o1 = ax * s0 + ay * c0;
    float o2 = bx * c1 - by * s1, o3 = bx * s1 + by * c1;

    bf16 h0, l0, h1, l1, h2, l2, h3, l3;
    split1(o0, h0, l0); split1(o1, h1, l1);
    split1(o2, h2, l2); split1(o3, h3, l3);
    ((bf162*)dh)[lane]      = bf162(h0, h1);
    ((bf162*)dl)[lane]      = bf162(l0, l1);
    ((bf162*)dh)[lane + 32] = bf162(h2, h3);
    ((bf162*)dl)[lane + 32] = bf162(l2, l3);
}

// ---------------------------------------------------------------------------
// Causal softmax reading fp32 scores, writing bf16 hi/lo probs.
// Zero-fills up to ceil128(s+1) (exactly the slack the K-limited PV reads).
// ---------------------------------------------------------------------------
__global__ void softmax_split_kernel(const float* __restrict__ scores,
                                     bf16* __restrict__ ph, bf16* __restrict__ pl) {
    int s = blockIdx.x, h = blockIdx.y;
    const float* row = scores + ((long long)h * S + s) * (long long)S;
    bf16* phr = ph + ((long long)h * S + s) * (long long)S;
    bf16* plr = pl + ((long long)h * S + s) * (long long)S;
    int n = s + 1;
    int nend = (n + 127) & ~127;
    int tid = threadIdx.x;

    float v[8];
    float mx = -FLT_MAX;
    #pragma unroll
    for (int i = 0; i < 8; i++) {
        int t = tid + i * 256;
        v[i] = (t < n) ? row[t] : -FLT_MAX;
        mx = fmaxf(mx, v[i]);
    }
    __shared__ float red[8];
    #pragma unroll
    for (int o = 16; o; o >>= 1) mx = fmaxf(mx, __shfl_xor_sync(0xFFFFFFFFu, mx, o));
    if ((tid & 31) == 0) red[tid >> 5] = mx;
    __syncthreads();
    mx = red[0];
    #pragma unroll
    for (int w = 1; w < 8; w++) mx = fmaxf(mx, red[w]);
    __syncthreads();

    float sum = 0.0f;
    #pragma unroll
    for (int i = 0; i < 8; i++) {
        int t = tid + i * 256;
        v[i] = (t < n) ? expf(v[i] - mx) : 0.0f;
        sum += v[i];
    }
    #pragma unroll
    for (int o = 16; o; o >>= 1) sum += __shfl_xor_sync(0xFFFFFFFFu, sum, o);
    if ((tid & 31) == 0) red[tid >> 5] = sum;
    __syncthreads();
    float tot = red[0];
    #pragma unroll
    for (int w = 1; w < 8; w++) tot += red[w];
    float inv = 1.0f / tot;

    #pragma unroll
    for (int i = 0; i < 8; i++) {
        int t = tid + i * 256;
        if (t < nend) {
            float pv = (t < n) ? v[i] * inv : 0.0f;
            bf16 hh, ll;
            split1(pv, hh, ll);
            phr[t] = hh; plr[t] = ll;
        }
    }
}

// ---------------------------------------------------------------------------
// Launch
// ---------------------------------------------------------------------------
extern "C" void kernel_launch(void* const* d_in, const int* in_sizes, int n_in,
                              void* d_out, int out_size) {
    const float* x     = (const float*)d_in[0];
    const float* w_qkv = (const float*)d_in[1];
    const float* w_out = (const float*)d_in[2];
    const float* qw    = (const float*)d_in[3];
    const float* kw    = (const float*)d_in[4];
    float* out = (float*)d_out;

    float *qkv, *scores, *cosT, *sinT;
    cudaGetSymbolAddress((void**)&qkv,    g_qkv);
    cudaGetSymbolAddress((void**)&scores, g_scores);
    cudaGetSymbolAddress((void**)&cosT,   g_cos);
    cudaGetSymbolAddress((void**)&sinT,   g_sin);
    bf16 *xh,*xl,*wqh,*wql,*woh,*wol,*qh,*ql,*kh,*kl,*vth,*vtl,*ph,*pl,*ah,*al;
    cudaGetSymbolAddress((void**)&xh,  g_xh);  cudaGetSymbolAddress((void**)&xl,  g_xl);
    cudaGetSymbolAddress((void**)&wqh, g_wqh); cudaGetSymbolAddress((void**)&wql, g_wql);
    cudaGetSymbolAddress((void**)&woh, g_woh); cudaGetSymbolAddress((void**)&wol, g_wol);
    cudaGetSymbolAddress((void**)&qh,  g_qh);  cudaGetSymbolAddress((void**)&ql,  g_ql);
    cudaGetSymbolAddress((void**)&kh,  g_kh);  cudaGetSymbolAddress((void**)&kl,  g_kl);
    cudaGetSymbolAddress((void**)&vth, g_vth); cudaGetSymbolAddress((void**)&vtl, g_vtl);
    cudaGetSymbolAddress((void**)&ph,  g_ph);  cudaGetSymbolAddress((void**)&pl,  g_pl);
    cudaGetSymbolAddress((void**)&ah,  g_ah);  cudaGetSymbolAddress((void**)&al,  g_al);

    const int SMEM = NSTG * STAGE_B;   // 61440
    cudaFuncSetAttribute(mma_gemm<0, 0>, cudaFuncAttributeMaxDynamicSharedMemorySize, SMEM);
    cudaFuncSetAttribute(mma_gemm<1, 0>, cudaFuncAttributeMaxDynamicSharedMemorySize, SMEM);
    cudaFuncSetAttribute(mma_gemm<2, 1>, cudaFuncAttributeMaxDynamicSharedMemorySize, SMEM);

    const float scale = 0.08838834764831845f;   // 1/sqrt(128)

    // #0 RoPE tables
    rope_table_kernel<<<(S * (HD / 2) + 255) / 256, 256>>>(cosT, sinT);

    // #1, #2: splits for QKV GEMM inputs
    {
        long long tx = (long long)S * D;
        split_kernel<<<(unsigned)((tx / 4 + 255) / 256), 256>>>(x, D, D, xh, xl, tx);
        long long tw = (long long)E * D;
        split_kernel<<<(unsigned)((tw / 4 + 255) / 256), 256>>>(w_qkv, D, D, wqh, wql, tw);
    }

    // #3 QKV projection: qkv = x @ w_qkv^T
    {
        dim3 grid(E / 128, S / 128, 1);
        mma_gemm<0, 0><<<grid, 256, SMEM>>>(xh, xl, wqh, wql, qkv, nullptr, nullptr,
                                            D, D, D, E, 0, 0, 0, 1, 1.0f);
    }

    // #4 RMSNorm + RoPE + split -> qh/ql, kh/kl
    rmsnorm_rope_split_kernel<<<S * (HQ + G) / 8, 256>>>(qkv, qw, kw, cosT, sinT,
                                                         qh, ql, kh, kl);

    // #5 scores[h] = scale * Q_h @ K_{h/4}^T  (causal tile skip)  [ncu target]
    {
        dim3 grid(S / 128, S / 128, HQ);
        mma_gemm<1, 0><<<grid, 256, SMEM>>>(qh, ql, kh, kl, scores, nullptr, nullptr,
                                            HD, D, G * HD, S,
                                            HD, HD, (long long)S * S, HG, scale);
    }

    // #6 V transpose + split (independent of QK; needed by PV)
    {
        dim3 vg(S, G);
        vsplit_kernel<<<vg, HD>>>(qkv, vth, vtl);
    }

    // #7 causal softmax -> bf16 hi/lo probs
    {
        dim3 grid(S, HQ);
        softmax_split_kernel<<<grid, 256>>>(scores, ph, pl);
    }

    // #8 attn cols h*128.. = P_h @ V_{h/4}^T  (K-limited), emits ah/al bf16
    {
        dim3 grid(1, S / 128, HQ);
        mma_gemm<2, 1><<<grid, 256, SMEM>>>(ph, pl, vth, vtl, nullptr, ah, al,
                                            S, S, S, D,
                                            (long long)S * S, (long long)HD * S, HD, HG, 1.0f);
    }

    // #9 split w_out (independent; placed late so QK GEMM is launch #5)
    {
        long long to = (long long)D * D;
        split_kernel<<<(unsigned)((to / 4 + 255) / 256), 256>>>(w_out, D, D, woh, wol, to);
    }

    // #10 out = attn @ w_out^T
    {
        dim3 grid(D / 128, S / 128, 1);
        mma_gemm<0, 0><<<grid, 256, SMEM>>>(ah, al, woh, wol, out, nullptr, nullptr,
                                            D, D, D, D, 0, 0, 0, 1, 1.0f);
    }
}

// round 9
// speedup vs baseline: 2.9883x; 1.1052x over previous
#include <cuda_runtime.h>
#include <cuda_bf16.h>
#include <math.h>
#include <float.h>
#include <stdint.h>

// Problem constants
#define S    2048
#define D    4096         // H*HD
#define HQ   32           // query heads
#define G    8            // kv heads
#define HD   128
#define E    6144         // D + 2*G*HD
#define HG   4            // HQ / G
#define EPSF 1e-5f

typedef __nv_bfloat16 bf16;
typedef __nv_bfloat162 bf162;

// ---------------------------------------------------------------------------
// Scratch (device globals; no runtime allocation allowed)
// ---------------------------------------------------------------------------
__device__ float g_qkv[(size_t)S * E];
__device__ float g_scores[(size_t)HQ * S * S];
__device__ float g_cos[(size_t)S * (HD / 2)];
__device__ float g_sin[(size_t)S * (HD / 2)];

__device__ bf16 g_xh[(size_t)S * D],        g_xl[(size_t)S * D];
__device__ bf16 g_wqh[(size_t)E * D],       g_wql[(size_t)E * D];
__device__ bf16 g_woh[(size_t)D * D],       g_wol[(size_t)D * D];
__device__ bf16 g_qh[(size_t)S * D],        g_ql[(size_t)S * D];
__device__ bf16 g_kh[(size_t)S * G * HD],   g_kl[(size_t)S * G * HD];
__device__ bf16 g_vth[(size_t)G * HD * S],  g_vtl[(size_t)G * HD * S];
__device__ bf16 g_ph[(size_t)HQ * S * S],   g_pl[(size_t)HQ * S * S];
__device__ bf16 g_ah[(size_t)S * D],        g_al[(size_t)S * D];

// ---------------------------------------------------------------------------
// Helpers
// ---------------------------------------------------------------------------
__device__ __forceinline__ uint32_t smem_u32_of(const void* p) {
    uint32_t a;
    asm("{ .reg .u64 t; cvta.to.shared.u64 t, %1; cvt.u32.u64 %0, t; }" : "=r"(a) : "l"(p));
    return a;
}

#define CP_ASYNC16(dst, src) \
    asm volatile("cp.async.cg.shared.global [%0], [%1], 16;" :: "r"(dst), "l"(src))
#define CP_COMMIT()  asm volatile("cp.async.commit_group;" ::: "memory")

#define LDMAT_X4(r0, r1, r2, r3, a) \
    asm volatile("ldmatrix.sync.aligned.m8n8.x4.shared.b16 {%0,%1,%2,%3}, [%4];" \
        : "=r"(r0), "=r"(r1), "=r"(r2), "=r"(r3) : "r"(a))

#define MMA16816(d, a, b0v, b1v) \
    asm volatile("mma.sync.aligned.m16n8k16.row.col.f32.bf16.bf16.f32 " \
        "{%0,%1,%2,%3}, {%4,%5,%6,%7}, {%8,%9}, {%0,%1,%2,%3};" \
        : "+f"((d)[0]), "+f"((d)[1]), "+f"((d)[2]), "+f"((d)[3]) \
        : "r"((a)[0]), "r"((a)[1]), "r"((a)[2]), "r"((a)[3]), "r"(b0v), "r"(b1v))

__device__ __forceinline__ void split1(float v, bf16& h, bf16& l) {
    h = __float2bfloat16(v);
    l = __float2bfloat16(v - __bfloat162float(h));
}

// ---------------------------------------------------------------------------
// Warp-MMA bf16x3 GEMM, merged planes:
//   C[M,N] = alpha * (Ah*Bh + Al*Bh + Ah*Bl)[M,K]x[N,K]^T   (fp32 accum)
// Per k-chunk, ALL FOUR tiles (Ah,Al,Bh,Bl) are loaded once and all three
// plane-MMAs issued against them (96 MMAs/iter) — 2/3 the global traffic and
// 1/3 the barrier count vs plane-sequential.
// Block tile 128x128x32, 256 thr (8 warps 2x4), warp tile 64x32.
// 2-stage cp.async double buffer, two __syncthreads per (triple-size) iter.
// 80B smem row stride (conflict-free ldmatrix, non-trans for [n][k] B).
//   CAUSAL 0: none | 1: skip tile if n0>=m0+128 (QK) | 2: K<=m0+128 (PV)
//   SPLITOUT 0: fp32 C | 1: bf16 hi/lo C pair
// Per-z offsets; B z-index = z / bzdiv (GQA).
// ---------------------------------------------------------------------------
#define RS      80                   // smem row stride bytes (32 bf16 + 16B pad)
#define TILE_B  (128 * RS)           // 10240 bytes per operand tile
#define STAGE_B (4 * TILE_B)         // Ah + Al + Bh + Bl per stage = 40960
#define NSTG    2

__device__ __forceinline__ void load_tile_async(uint32_t sdst, const bf16* src,
                                                int ld, int tid) {
    #pragma unroll
    for (int it = 0; it < 2; it++) {
        int idx = tid + it * 256;
        int row = idx >> 2, ch = idx & 3;
        const bf16* g = src + (long long)row * ld + ch * 8;
        CP_ASYNC16(sdst + row * RS + ch * 16, g);
    }
}

template <int CAUSAL, int SPLITOUT>
__global__ void __launch_bounds__(256, 2)
mma_gemm(const bf16* __restrict__ Ah, const bf16* __restrict__ Al,
         const bf16* __restrict__ Bh, const bf16* __restrict__ Bl,
         float* __restrict__ C, bf16* __restrict__ Ch, bf16* __restrict__ Cl,
         int K, int lda, int ldb, int ldc,
         long long sAz, long long sBz, long long sCz, int bzdiv, float alpha) {
    int m0 = blockIdx.y * 128;
    int n0 = blockIdx.x * 128;
    if (CAUSAL == 1 && n0 >= m0 + 128) return;

    int z = blockIdx.z;
    const bf16* AhZ = Ah + (long long)z * sAz + (long long)m0 * lda;
    const bf16* AlZ = Al + (long long)z * sAz + (long long)m0 * lda;
    const bf16* BhZ = Bh + (long long)(z / bzdiv) * sBz + (long long)n0 * ldb;
    const bf16* BlZ = Bl + (long long)(z / bzdiv) * sBz + (long long)n0 * ldb;

    int Keff = (CAUSAL == 2) ? ((K < m0 + 128) ? K : (m0 + 128)) : K;
    int NT   = Keff >> 5;            // k-chunks of 32

    extern __shared__ __align__(16) char smem[];     // NSTG * STAGE_B
    uint32_t smb = smem_u32_of(smem);

    int tid  = threadIdx.x;
    int warp = tid >> 5, lane = tid & 31;
    int wm = (warp >> 2) * 64;       // warp row offset (2 warps in m)
    int wn = (warp & 3) * 32;        // warp col offset (4 warps in n)

    float acc[4][4][4];
    #pragma unroll
    for (int i = 0; i < 4; i++)
        #pragma unroll
        for (int j = 0; j < 4; j++)
            #pragma unroll
            for (int t = 0; t < 4; t++) acc[i][j][t] = 0.0f;

    // per-lane ldmatrix base offsets (within one operand tile)
    uint32_t aLane = (uint32_t)((wm + (lane & 15)) * RS + (lane >> 4) * 16);
    uint32_t bLane = (uint32_t)((wn + ((lane >> 4) << 3) + (lane & 7)) * RS
                                + ((lane >> 3) & 1) * 16);

    auto load_stage = [&](int kc, uint32_t sb) {
        const bf16* a_h = AhZ + kc * 32;
        const bf16* a_l = AlZ + kc * 32;
        const bf16* b_h = BhZ + kc * 32;
        const bf16* b_l = BlZ + kc * 32;
        load_tile_async(sb,              a_h, lda, tid);
        load_tile_async(sb + TILE_B,     a_l, lda, tid);
        load_tile_async(sb + 2 * TILE_B, b_h, ldb, tid);
        load_tile_async(sb + 3 * TILE_B, b_l, ldb, tid);
    };

    // prologue: stage 0
    load_stage(0, smb);
    CP_COMMIT();

    for (int i = 0; i < NT; i++) {
        // issue next stage into the other slot, then wait for stage i
        if (i + 1 < NT) {
            load_stage(i + 1, smb + ((i + 1) & 1) * STAGE_B);
            CP_COMMIT();
            asm volatile("cp.async.wait_group 1;" ::: "memory");
        } else {
            asm volatile("cp.async.wait_group 0;" ::: "memory");
        }
        __syncthreads();

        uint32_t sb  = smb + (i & 1) * STAGE_B;
        uint32_t aHA = sb + aLane;
        uint32_t aLA = sb + TILE_B + aLane;
        uint32_t bHA = sb + 2 * TILE_B + bLane;
        uint32_t bLA = sb + 3 * TILE_B + bLane;

        #pragma unroll
        for (int kk = 0; kk < 2; kk++) {           // two k16 steps per chunk
            uint32_t bh[2][4], bl[2][4];
            #pragma unroll
            for (int nb2 = 0; nb2 < 2; nb2++) {
                LDMAT_X4(bh[nb2][0], bh[nb2][1], bh[nb2][2], bh[nb2][3],
                         bHA + nb2 * (16 * RS) + kk * 32);
                LDMAT_X4(bl[nb2][0], bl[nb2][1], bl[nb2][2], bl[nb2][3],
                         bLA + nb2 * (16 * RS) + kk * 32);
            }
            #pragma unroll
            for (int ma = 0; ma < 4; ma++) {
                uint32_t ah[4], al[4];
                LDMAT_X4(ah[0], ah[1], ah[2], ah[3],
                         aHA + ma * (16 * RS) + kk * 32);
                LDMAT_X4(al[0], al[1], al[2], al[3],
                         aLA + ma * (16 * RS) + kk * 32);
                #pragma unroll
                for (int nb2 = 0; nb2 < 2; nb2++) {
                    MMA16816(acc[ma][nb2 * 2 + 0], ah, bh[nb2][0], bh[nb2][1]);
                    MMA16816(acc[ma][nb2 * 2 + 1], ah, bh[nb2][2], bh[nb2][3]);
                    MMA16816(acc[ma][nb2 * 2 + 0], al, bh[nb2][0], bh[nb2][1]);
                    MMA16816(acc[ma][nb2 * 2 + 1], al, bh[nb2][2], bh[nb2][3]);
                    MMA16816(acc[ma][nb2 * 2 + 0], ah, bl[nb2][0], bl[nb2][1]);
                    MMA16816(acc[ma][nb2 * 2 + 1], ah, bl[nb2][2], bl[nb2][3]);
                }
            }
        }
        // protect this slot from the NEXT iteration's cp.async overwrite
        __syncthreads();
    }

    // epilogue
    int group = lane >> 2, tig = lane & 3;
    #pragma unroll
    for (int ma = 0; ma < 4; ma++) {
        int r0 = m0 + wm + ma * 16 + group;
        #pragma unroll
        for (int na = 0; na < 4; na++) {
            int c = n0 + wn + na * 8 + tig * 2;
            #pragma unroll
            for (int half = 0; half < 2; half++) {
                long long off = (long long)(r0 + half * 8) * ldc + c
                              + (long long)z * sCz;
                float v0 = acc[ma][na][half * 2 + 0] * alpha;
                float v1 = acc[ma][na][half * 2 + 1] * alpha;
                if (SPLITOUT) {
                    bf16 h0, l0, h1, l1;
                    split1(v0, h0, l0); split1(v1, h1, l1);
                    *(bf162*)(Ch + off) = bf162(h0, h1);
                    *(bf162*)(Cl + off) = bf162(l0, l1);
                } else {
                    *(float2*)(C + off) = make_float2(v0, v1);
                }
            }
        }
    }
}

// ---------------------------------------------------------------------------
// fp32 -> bf16 hi/lo split (2D strided source, contiguous dest)
// ---------------------------------------------------------------------------
__global__ void split_kernel(const float* __restrict__ src, int ldsrc, int cols,
                             bf16* __restrict__ hi, bf16* __restrict__ lo,
                             long long total) {
    long long i4 = ((long long)blockIdx.x * blockDim.x + threadIdx.x) * 4;
    if (i4 >= total) return;
    long long r = i4 / cols;
    int c = (int)(i4 - r * cols);
    float4 v = *(const float4*)(src + r * (long long)ldsrc + c);
    bf16 h0, l0, h1, l1, h2, l2, h3, l3;
    split1(v.x, h0, l0); split1(v.y, h1, l1);
    split1(v.z, h2, l2); split1(v.w, h3, l3);
    *(bf162*)(hi + i4)     = bf162(h0, h1);
    *(bf162*)(hi + i4 + 2) = bf162(h2, h3);
    *(bf162*)(lo + i4)     = bf162(l0, l1);
    *(bf162*)(lo + i4 + 2) = bf162(l2, l3);
}

// V transpose + split: vt[g][d][t] = split(qkv[t, D + G*HD + g*HD + d])
__global__ void vsplit_kernel(const float* __restrict__ qkv,
                              bf16* __restrict__ vth, bf16* __restrict__ vtl) {
    int t = blockIdx.x, g = blockIdx.y, d = threadIdx.x;
    float v = qkv[(long long)t * E + D + G * HD + g * HD + d];
    bf16 h, l;
    split1(v, h, l);
    long long o = ((long long)(g * HD + d)) * S + t;
    vth[o] = h; vtl[o] = l;
}

// ---------------------------------------------------------------------------
// RoPE cos/sin table (matches reference fp32 semantics)
// ---------------------------------------------------------------------------
__global__ void rope_table_kernel(float* __restrict__ cosT, float* __restrict__ sinT) {
    int idx = blockIdx.x * blockDim.x + threadIdx.x;
    if (idx >= S * (HD / 2)) return;
    int s = idx >> 6;
    int i = idx & 63;
    double freq_d = pow(1.0e6, -(double)(2 * i) / 128.0);
    float  ang = (float)s * (float)freq_d;
    double cd, sd;
    sincos((double)ang, &sd, &cd);
    cosT[idx] = (float)cd;
    sinT[idx] = (float)sd;
}

// ---------------------------------------------------------------------------
// Fused RMSNorm + RoPE + bf16 hi/lo split. Reads fp32 q/k from g_qkv,
// writes qh/ql (dense [S,D]) and kh/kl (dense [S,G*HD]). One warp per row.
// ---------------------------------------------------------------------------
__global__ void rmsnorm_rope_split_kernel(const float* __restrict__ qkv,
                                          const float* __restrict__ qw,
                                          const float* __restrict__ kw,
                                          const float* __restrict__ cosT,
                                          const float* __restrict__ sinT,
                                          bf16* __restrict__ qh, bf16* __restrict__ ql,
                                          bf16* __restrict__ kh, bf16* __restrict__ kl) {
    int gwarp = (blockIdx.x * blockDim.x + threadIdx.x) >> 5;
    int lane  = threadIdx.x & 31;
    const int NROWS = S * (HQ + G);
    if (gwarp >= NROWS) return;
    int s  = gwarp / (HQ + G);
    int hh = gwarp % (HQ + G);

    const float* row;
    const float* w;
    bf16 *dh, *dl;
    if (hh < HQ) {
        row = qkv + (long long)s * E + hh * HD;            w = qw;
        dh = qh + (long long)s * D + hh * HD;
        dl = ql + (long long)s * D + hh * HD;
    } else {
        row = qkv + (long long)s * E + D + (hh - HQ) * HD; w = kw;
        dh = kh + (long long)s * (G * HD) + (hh - HQ) * HD;
        dl = kl + (long long)s * (G * HD) + (hh - HQ) * HD;
    }

    const float2* row2 = (const float2*)row;
    float2 a = row2[lane], b = row2[lane + 32];
    float ss = a.x * a.x + a.y * a.y + b.x * b.x + b.y * b.y;
    #pragma unroll
    for (int o = 16; o; o >>= 1) ss += __shfl_xor_sync(0xFFFFFFFFu, ss, o);
    float r = rsqrtf(ss * (1.0f / 128.0f) + EPSF);

    const float2* w2 = (const float2*)w;
    float2 wa = w2[lane], wb = w2[lane + 32];
    float ax = (a.x * r) * wa.x, ay = (a.y * r) * wa.y;
    float bx = (b.x * r) * wb.x, by = (b.y * r) * wb.y;

    int base = s * (HD / 2);
    float c0 = cosT[base + lane],      s0 = sinT[base + lane];
    float c1 = cosT[base + lane + 32], s1 = sinT[base + lane + 32];

    float o0 = ax * c0 - ay * s0, o1 = ax * s0 + ay * c0;
    float o2 = bx * c1 - by * s1, o3 = bx * s1 + by * c1;

    bf16 h0, l0, h1, l1, h2, l2, h3, l3;
    split1(o0, h0, l0); split1(o1, h1, l1);
    split1(o2, h2, l2); split1(o3, h3, l3);
    ((bf162*)dh)[lane]      = bf162(h0, h1);
    ((bf162*)dl)[lane]      = bf162(l0, l1);
    ((bf162*)dh)[lane + 32] = bf162(h2, h3);
    ((bf162*)dl)[lane + 32] = bf162(l2, l3);
}

// ---------------------------------------------------------------------------
// Causal softmax reading fp32 scores, writing bf16 hi/lo probs.
// Zero-fills up to ceil128(s+1) (exactly the slack the K-limited PV reads).
// ---------------------------------------------------------------------------
__global__ void softmax_split_kernel(const float* __restrict__ scores,
                                     bf16* __restrict__ ph, bf16* __restrict__ pl) {
    int s = blockIdx.x, h = blockIdx.y;
    const float* row = scores + ((long long)h * S + s) * (long long)S;
    bf16* phr = ph + ((long long)h * S + s) * (long long)S;
    bf16* plr = pl + ((long long)h * S + s) * (long long)S;
    int n = s + 1;
    int nend = (n + 127) & ~127;
    int tid = threadIdx.x;

    float v[8];
    float mx = -FLT_MAX;
    #pragma unroll
    for (int i = 0; i < 8; i++) {
        int t = tid + i * 256;
        v[i] = (t < n) ? row[t] : -FLT_MAX;
        mx = fmaxf(mx, v[i]);
    }
    __shared__ float red[8];
    #pragma unroll
    for (int o = 16; o; o >>= 1) mx = fmaxf(mx, __shfl_xor_sync(0xFFFFFFFFu, mx, o));
    if ((tid & 31) == 0) red[tid >> 5] = mx;
    __syncthreads();
    mx = red[0];
    #pragma unroll
    for (int w = 1; w < 8; w++) mx = fmaxf(mx, red[w]);
    __syncthreads();

    float sum = 0.0f;
    #pragma unroll
    for (int i = 0; i < 8; i++) {
        int t = tid + i * 256;
        v[i] = (t < n) ? expf(v[i] - mx) : 0.0f;
        sum += v[i];
    }
    #pragma unroll
    for (int o = 16; o; o >>= 1) sum += __shfl_xor_sync(0xFFFFFFFFu, sum, o);
    if ((tid & 31) == 0) red[tid >> 5] = sum;
    __syncthreads();
    float tot = red[0];
    #pragma unroll
    for (int w = 1; w < 8; w++) tot += red[w];
    float inv = 1.0f / tot;

    #pragma unroll
    for (int i = 0; i < 8; i++) {
        int t = tid + i * 256;
        if (t < nend) {
            float pv = (t < n) ? v[i] * inv : 0.0f;
            bf16 hh, ll;
            split1(pv, hh, ll);
            phr[t] = hh; plr[t] = ll;
        }
    }
}

// ---------------------------------------------------------------------------
// Launch
// ---------------------------------------------------------------------------
extern "C" void kernel_launch(void* const* d_in, const int* in_sizes, int n_in,
                              void* d_out, int out_size) {
    const float* x     = (const float*)d_in[0];
    const float* w_qkv = (const float*)d_in[1];
    const float* w_out = (const float*)d_in[2];
    const float* qw    = (const float*)d_in[3];
    const float* kw    = (const float*)d_in[4];
    float* out = (float*)d_out;

    float *qkv, *scores, *cosT, *sinT;
    cudaGetSymbolAddress((void**)&qkv,    g_qkv);
    cudaGetSymbolAddress((void**)&scores, g_scores);
    cudaGetSymbolAddress((void**)&cosT,   g_cos);
    cudaGetSymbolAddress((void**)&sinT,   g_sin);
    bf16 *xh,*xl,*wqh,*wql,*woh,*wol,*qh,*ql,*kh,*kl,*vth,*vtl,*ph,*pl,*ah,*al;
    cudaGetSymbolAddress((void**)&xh,  g_xh);  cudaGetSymbolAddress((void**)&xl,  g_xl);
    cudaGetSymbolAddress((void**)&wqh, g_wqh); cudaGetSymbolAddress((void**)&wql, g_wql);
    cudaGetSymbolAddress((void**)&woh, g_woh); cudaGetSymbolAddress((void**)&wol, g_wol);
    cudaGetSymbolAddress((void**)&qh,  g_qh);  cudaGetSymbolAddress((void**)&ql,  g_ql);
    cudaGetSymbolAddress((void**)&kh,  g_kh);  cudaGetSymbolAddress((void**)&kl,  g_kl);
    cudaGetSymbolAddress((void**)&vth, g_vth); cudaGetSymbolAddress((void**)&vtl, g_vtl);
    cudaGetSymbolAddress((void**)&ph,  g_ph);  cudaGetSymbolAddress((void**)&pl,  g_pl);
    cudaGetSymbolAddress((void**)&ah,  g_ah);  cudaGetSymbolAddress((void**)&al,  g_al);

    const int SMEM = NSTG * STAGE_B;   // 81920
    cudaFuncSetAttribute(mma_gemm<0, 0>, cudaFuncAttributeMaxDynamicSharedMemorySize, SMEM);
    cudaFuncSetAttribute(mma_gemm<1, 0>, cudaFuncAttributeMaxDynamicSharedMemorySize, SMEM);
    cudaFuncSetAttribute(mma_gemm<2, 1>, cudaFuncAttributeMaxDynamicSharedMemorySize, SMEM);

    const float scale = 0.08838834764831845f;   // 1/sqrt(128)

    // #0 RoPE tables
    rope_table_kernel<<<(S * (HD / 2) + 255) / 256, 256>>>(cosT, sinT);

    // #1, #2: splits for QKV GEMM inputs
    {
        long long tx = (long long)S * D;
        split_kernel<<<(unsigned)((tx / 4 + 255) / 256), 256>>>(x, D, D, xh, xl, tx);
        long long tw = (long long)E * D;
        split_kernel<<<(unsigned)((tw / 4 + 255) / 256), 256>>>(w_qkv, D, D, wqh, wql, tw);
    }

    // #3 QKV projection: qkv = x @ w_qkv^T
    {
        dim3 grid(E / 128, S / 128, 1);
        mma_gemm<0, 0><<<grid, 256, SMEM>>>(xh, xl, wqh, wql, qkv, nullptr, nullptr,
                                            D, D, D, E, 0, 0, 0, 1, 1.0f);
    }

    // #4 RMSNorm + RoPE + split -> qh/ql, kh/kl
    rmsnorm_rope_split_kernel<<<S * (HQ + G) / 8, 256>>>(qkv, qw, kw, cosT, sinT,
                                                         qh, ql, kh, kl);

    // #5 scores[h] = scale * Q_h @ K_{h/4}^T  (causal tile skip)  [ncu target]
    {
        dim3 grid(S / 128, S / 128, HQ);
        mma_gemm<1, 0><<<grid, 256, SMEM>>>(qh, ql, kh, kl, scores, nullptr, nullptr,
                                            HD, D, G * HD, S,
                                            HD, HD, (long long)S * S, HG, scale);
    }

    // #6 V transpose + split (independent of QK; needed by PV)
    {
        dim3 vg(S, G);
        vsplit_kernel<<<vg, HD>>>(qkv, vth, vtl);
    }

    // #7 causal softmax -> bf16 hi/lo probs
    {
        dim3 grid(S, HQ);
        softmax_split_kernel<<<grid, 256>>>(scores, ph, pl);
    }

    // #8 attn cols h*128.. = P_h @ V_{h/4}^T  (K-limited), emits ah/al bf16
    {
        dim3 grid(1, S / 128, HQ);
        mma_gemm<2, 1><<<grid, 256, SMEM>>>(ph, pl, vth, vtl, nullptr, ah, al,
                                            S, S, S, D,
                                            (long long)S * S, (long long)HD * S, HD, HG, 1.0f);
    }

    // #9 split w_out (independent; placed late so QK GEMM is launch #5)
    {
        long long to = (long long)D * D;
        split_kernel<<<(unsigned)((to / 4 + 255) / 256), 256>>>(w_out, D, D, woh, wol, to);
    }

    // #10 out = attn @ w_out^T
    {
        dim3 grid(D / 128, S / 128, 1);
        mma_gemm<0, 0><<<grid, 256, SMEM>>>(ah, al, woh, wol, out, nullptr, nullptr,
                                            D, D, D, D, 0, 0, 0, 1, 1.0f);
    }
}

// round 12
// speedup vs baseline: 3.0193x; 1.0104x over previous
#include <cuda_runtime.h>
#include <cuda_bf16.h>
#include <math.h>
#include <float.h>
#include <stdint.h>

// Problem constants
#define S    2048
#define D    4096         // H*HD
#define HQ   32           // query heads
#define G    8            // kv heads
#define HD   128
#define E    6144         // D + 2*G*HD
#define HG   4            // HQ / G
#define EPSF 1e-5f

typedef __nv_bfloat16 bf16;
typedef __nv_bfloat162 bf162;

// ---------------------------------------------------------------------------
// Scratch (device globals; no runtime allocation allowed)
// ---------------------------------------------------------------------------
__device__ float g_qkv[(size_t)S * E];
__device__ float g_scores[(size_t)HQ * S * S];
__device__ float g_cos[(size_t)S * (HD / 2)];
__device__ float g_sin[(size_t)S * (HD / 2)];

__device__ bf16 g_xh[(size_t)S * D],        g_xl[(size_t)S * D];
__device__ bf16 g_wqh[(size_t)E * D],       g_wql[(size_t)E * D];
__device__ bf16 g_woh[(size_t)D * D],       g_wol[(size_t)D * D];
__device__ bf16 g_qh[(size_t)S * D],        g_ql[(size_t)S * D];
__device__ bf16 g_kh[(size_t)S * G * HD],   g_kl[(size_t)S * G * HD];
__device__ bf16 g_vth[(size_t)G * HD * S],  g_vtl[(size_t)G * HD * S];
__device__ bf16 g_ph[(size_t)HQ * S * S],   g_pl[(size_t)HQ * S * S];
__device__ bf16 g_ah[(size_t)S * D],        g_al[(size_t)S * D];

// ---------------------------------------------------------------------------
// Helpers
// ---------------------------------------------------------------------------
__device__ __forceinline__ uint32_t smem_u32_of(const void* p) {
    uint32_t a;
    asm("{ .reg .u64 t; cvta.to.shared.u64 t, %1; cvt.u32.u64 %0, t; }" : "=r"(a) : "l"(p));
    return a;
}

#define CP_ASYNC16(dst, src) \
    asm volatile("cp.async.cg.shared.global [%0], [%1], 16;" :: "r"(dst), "l"(src))
#define CP_COMMIT()  asm volatile("cp.async.commit_group;" ::: "memory")

#define LDMAT_X4(r0, r1, r2, r3, a) \
    asm volatile("ldmatrix.sync.aligned.m8n8.x4.shared.b16 {%0,%1,%2,%3}, [%4];" \
        : "=r"(r0), "=r"(r1), "=r"(r2), "=r"(r3) : "r"(a))

#define MMA16816(d, a, b0v, b1v) \
    asm volatile("mma.sync.aligned.m16n8k16.row.col.f32.bf16.bf16.f32 " \
        "{%0,%1,%2,%3}, {%4,%5,%6,%7}, {%8,%9}, {%0,%1,%2,%3};" \
        : "+f"((d)[0]), "+f"((d)[1]), "+f"((d)[2]), "+f"((d)[3]) \
        : "r"((a)[0]), "r"((a)[1]), "r"((a)[2]), "r"((a)[3]), "r"(b0v), "r"(b1v))

__device__ __forceinline__ void split1(float v, bf16& h, bf16& l) {
    h = __float2bfloat16(v);
    l = __float2bfloat16(v - __bfloat162float(h));
}

// ---------------------------------------------------------------------------
// Warp-MMA bf16x3 GEMM, merged planes, plane-major MMA ordering:
//   C[M,N] = alpha * (Ah*Bh + Al*Bh + Ah*Bl)[M,K]x[N,K]^T   (fp32 accum)
// Per k-chunk all four tiles (Ah,Al,Bh,Bl) loaded once; within an ma-pair the
// three plane sweeps each touch 8 distinct acc blocks before any acc is
// revisited (reuse distance 8 MMAs) — hides tensor-pipe RAW latency.
// Block tile 128x128x32, 256 thr (8 warps 2x4), warp tile 64x32.
// 2-stage cp.async double buffer; 80B smem row stride (conflict-free).
//   CAUSAL 0: none | 1: skip tile if n0>=m0+128 (QK) | 2: K<=m0+128 (PV)
//   SPLITOUT 0: fp32 C | 1: bf16 hi/lo C pair
// Per-z offsets; B z-index = z / bzdiv (GQA).
// ---------------------------------------------------------------------------
#define RS      80                   // smem row stride bytes (32 bf16 + 16B pad)
#define TILE_B  (128 * RS)           // 10240 bytes per operand tile
#define STAGE_B (4 * TILE_B)         // Ah + Al + Bh + Bl per stage = 40960
#define NSTG    2

__device__ __forceinline__ void load_tile_async(uint32_t sdst, const bf16* src,
                                                int ld, int tid) {
    #pragma unroll
    for (int it = 0; it < 2; it++) {
        int idx = tid + it * 256;
        int row = idx >> 2, ch = idx & 3;
        const bf16* g = src + (long long)row * ld + ch * 8;
        CP_ASYNC16(sdst + row * RS + ch * 16, g);
    }
}

template <int CAUSAL, int SPLITOUT>
__global__ void __launch_bounds__(256, 2)
mma_gemm(const bf16* __restrict__ Ah, const bf16* __restrict__ Al,
         const bf16* __restrict__ Bh, const bf16* __restrict__ Bl,
         float* __restrict__ C, bf16* __restrict__ Ch, bf16* __restrict__ Cl,
         int K, int lda, int ldb, int ldc,
         long long sAz, long long sBz, long long sCz, int bzdiv, float alpha) {
    int m0 = blockIdx.y * 128;
    int n0 = blockIdx.x * 128;
    if (CAUSAL == 1 && n0 >= m0 + 128) return;

    int z = blockIdx.z;
    const bf16* AhZ = Ah + (long long)z * sAz + (long long)m0 * lda;
    const bf16* AlZ = Al + (long long)z * sAz + (long long)m0 * lda;
    const bf16* BhZ = Bh + (long long)(z / bzdiv) * sBz + (long long)n0 * ldb;
    const bf16* BlZ = Bl + (long long)(z / bzdiv) * sBz + (long long)n0 * ldb;

    int Keff = (CAUSAL == 2) ? ((K < m0 + 128) ? K : (m0 + 128)) : K;
    int NT   = Keff >> 5;            // k-chunks of 32

    extern __shared__ __align__(16) char smem[];     // NSTG * STAGE_B
    uint32_t smb = smem_u32_of(smem);

    int tid  = threadIdx.x;
    int warp = tid >> 5, lane = tid & 31;
    int wm = (warp >> 2) * 64;       // warp row offset (2 warps in m)
    int wn = (warp & 3) * 32;        // warp col offset (4 warps in n)

    float acc[4][4][4];
    #pragma unroll
    for (int i = 0; i < 4; i++)
        #pragma unroll
        for (int j = 0; j < 4; j++)
            #pragma unroll
            for (int t = 0; t < 4; t++) acc[i][j][t] = 0.0f;

    // per-lane ldmatrix base offsets (within one operand tile)
    uint32_t aLane = (uint32_t)((wm + (lane & 15)) * RS + (lane >> 4) * 16);
    uint32_t bLane = (uint32_t)((wn + ((lane >> 4) << 3) + (lane & 7)) * RS
                                + ((lane >> 3) & 1) * 16);

    auto load_stage = [&](int kc, uint32_t sb) {
        load_tile_async(sb,              AhZ + kc * 32, lda, tid);
        load_tile_async(sb + TILE_B,     AlZ + kc * 32, lda, tid);
        load_tile_async(sb + 2 * TILE_B, BhZ + kc * 32, ldb, tid);
        load_tile_async(sb + 3 * TILE_B, BlZ + kc * 32, ldb, tid);
    };

    // prologue: stage 0
    load_stage(0, smb);
    CP_COMMIT();

    for (int i = 0; i < NT; i++) {
        if (i + 1 < NT) {
            load_stage(i + 1, smb + ((i + 1) & 1) * STAGE_B);
            CP_COMMIT();
            asm volatile("cp.async.wait_group 1;" ::: "memory");
        } else {
            asm volatile("cp.async.wait_group 0;" ::: "memory");
        }
        __syncthreads();

        uint32_t sb  = smb + (i & 1) * STAGE_B;
        uint32_t aHA = sb + aLane;
        uint32_t aLA = sb + TILE_B + aLane;
        uint32_t bHA = sb + 2 * TILE_B + bLane;
        uint32_t bLA = sb + 3 * TILE_B + bLane;

        #pragma unroll
        for (int kk = 0; kk < 2; kk++) {           // two k16 steps per chunk
            uint32_t bh[2][4], bl[2][4];
            #pragma unroll
            for (int nb2 = 0; nb2 < 2; nb2++) {
                LDMAT_X4(bh[nb2][0], bh[nb2][1], bh[nb2][2], bh[nb2][3],
                         bHA + nb2 * (16 * RS) + kk * 32);
                LDMAT_X4(bl[nb2][0], bl[nb2][1], bl[nb2][2], bl[nb2][3],
                         bLA + nb2 * (16 * RS) + kk * 32);
            }
            #pragma unroll
            for (int mp = 0; mp < 2; mp++) {       // ma-pairs {0,1},{2,3}
                uint32_t ah[2][4], al[2][4];
                #pragma unroll
                for (int mi = 0; mi < 2; mi++) {
                    int ma = mp * 2 + mi;
                    LDMAT_X4(ah[mi][0], ah[mi][1], ah[mi][2], ah[mi][3],
                             aHA + ma * (16 * RS) + kk * 32);
                    LDMAT_X4(al[mi][0], al[mi][1], al[mi][2], al[mi][3],
                             aLA + ma * (16 * RS) + kk * 32);
                }
                // plane 0: ah x bh — 8 distinct acc blocks
                #pragma unroll
                for (int mi = 0; mi < 2; mi++)
                    #pragma unroll
                    for (int nb2 = 0; nb2 < 2; nb2++) {
                        MMA16816(acc[mp * 2 + mi][nb2 * 2 + 0], ah[mi], bh[nb2][0], bh[nb2][1]);
                        MMA16816(acc[mp * 2 + mi][nb2 * 2 + 1], ah[mi], bh[nb2][2], bh[nb2][3]);
                    }
                // plane 1: al x bh
                #pragma unroll
                for (int mi = 0; mi < 2; mi++)
                    #pragma unroll
                    for (int nb2 = 0; nb2 < 2; nb2++) {
                        MMA16816(acc[mp * 2 + mi][nb2 * 2 + 0], al[mi], bh[nb2][0], bh[nb2][1]);
                        MMA16816(acc[mp * 2 + mi][nb2 * 2 + 1], al[mi], bh[nb2][2], bh[nb2][3]);
                    }
                // plane 2: ah x bl
                #pragma unroll
                for (int mi = 0; mi < 2; mi++)
                    #pragma unroll
                    for (int nb2 = 0; nb2 < 2; nb2++) {
                        MMA16816(acc[mp * 2 + mi][nb2 * 2 + 0], ah[mi], bl[nb2][0], bl[nb2][1]);
                        MMA16816(acc[mp * 2 + mi][nb2 * 2 + 1], ah[mi], bl[nb2][2], bl[nb2][3]);
                    }
            }
        }
        __syncthreads();   // protect this slot from next iteration's cp.async
    }

    // epilogue
    int group = lane >> 2, tig = lane & 3;
    #pragma unroll
    for (int ma = 0; ma < 4; ma++) {
        int r0 = m0 + wm + ma * 16 + group;
        #pragma unroll
        for (int na = 0; na < 4; na++) {
            int c = n0 + wn + na * 8 + tig * 2;
            #pragma unroll
            for (int half = 0; half < 2; half++) {
                long long off = (long long)(r0 + half * 8) * ldc + c
                              + (long long)z * sCz;
                float v0 = acc[ma][na][half * 2 + 0] * alpha;
                float v1 = acc[ma][na][half * 2 + 1] * alpha;
                if (SPLITOUT) {
                    bf16 h0, l0, h1, l1;
                    split1(v0, h0, l0); split1(v1, h1, l1);
                    *(bf162*)(Ch + off) = bf162(h0, h1);
                    *(bf162*)(Cl + off) = bf162(l0, l1);
                } else {
                    *(float2*)(C + off) = make_float2(v0, v1);
                }
            }
        }
    }
}

// ---------------------------------------------------------------------------
// fp32 -> bf16 hi/lo split (2D strided source, contiguous dest)
// ---------------------------------------------------------------------------
__global__ void split_kernel(const float* __restrict__ src, int ldsrc, int cols,
                             bf16* __restrict__ hi, bf16* __restrict__ lo,
                             long long total) {
    long long i4 = ((long long)blockIdx.x * blockDim.x + threadIdx.x) * 4;
    if (i4 >= total) return;
    long long r = i4 / cols;
    int c = (int)(i4 - r * cols);
    float4 v = *(const float4*)(src + r * (long long)ldsrc + c);
    bf16 h0, l0, h1, l1, h2, l2, h3, l3;
    split1(v.x, h0, l0); split1(v.y, h1, l1);
    split1(v.z, h2, l2); split1(v.w, h3, l3);
    *(bf162*)(hi + i4)     = bf162(h0, h1);
    *(bf162*)(hi + i4 + 2) = bf162(h2, h3);
    *(bf162*)(lo + i4)     = bf162(l0, l1);
    *(bf162*)(lo + i4 + 2) = bf162(l2, l3);
}

// V transpose + split via smem tiles (coalesced both sides).
// Source: qkv[t][D + G*HD + c], c in [0,1024). Dest: vt[c][t], [1024][S].
__global__ void vsplit_kernel(const float* __restrict__ qkv,
                              bf16* __restrict__ vth, bf16* __restrict__ vtl) {
    __shared__ float tile[32][33];
    int tbase = blockIdx.x * 32;       // t tile
    int cbase = blockIdx.y * 32;       // c tile
    int tx = threadIdx.x, ty = threadIdx.y;   // 32 x 8
    #pragma unroll
    for (int j = 0; j < 4; j++) {
        int row = ty + j * 8;          // t offset
        tile[row][tx] = qkv[(long long)(tbase + row) * E + D + G * HD + cbase + tx];
    }
    __syncthreads();
    #pragma unroll
    for (int j = 0; j < 4; j++) {
        int c = cbase + ty + j * 8;
        float v = tile[tx][ty + j * 8];
        bf16 h, l;
        split1(v, h, l);
        long long o = (long long)c * S + tbase + tx;
        vth[o] = h; vtl[o] = l;
    }
}

// ---------------------------------------------------------------------------
// RoPE cos/sin table (matches reference fp32 semantics)
// ---------------------------------------------------------------------------
__global__ void rope_table_kernel(float* __restrict__ cosT, float* __restrict__ sinT) {
    int idx = blockIdx.x * blockDim.x + threadIdx.x;
    if (idx >= S * (HD / 2)) return;
    int s = idx >> 6;
    int i = idx & 63;
    double freq_d = pow(1.0e6, -(double)(2 * i) / 128.0);
    float  ang = (float)s * (float)freq_d;
    double cd, sd;
    sincos((double)ang, &sd, &cd);
    cosT[idx] = (float)cd;
    sinT[idx] = (float)sd;
}

// ---------------------------------------------------------------------------
// Fused RMSNorm + RoPE + bf16 hi/lo split. Reads fp32 q/k from g_qkv,
// writes qh/ql (dense [S,D]) and kh/kl (dense [S,G*HD]). One warp per row.
// ---------------------------------------------------------------------------
__global__ void rmsnorm_rope_split_kernel(const float* __restrict__ qkv,
                                          const float* __restrict__ qw,
                                          const float* __restrict__ kw,
                                          const float* __restrict__ cosT,
                                          const float* __restrict__ sinT,
                                          bf16* __restrict__ qh, bf16* __restrict__ ql,
                                          bf16* __restrict__ kh, bf16* __restrict__ kl) {
    int gwarp = (blockIdx.x * blockDim.x + threadIdx.x) >> 5;
    int lane  = threadIdx.x & 31;
    const int NROWS = S * (HQ + G);
    if (gwarp >= NROWS) return;
    int s  = gwarp / (HQ + G);
    int hh = gwarp % (HQ + G);

    const float* row;
    const float* w;
    bf16 *dh, *dl;
    if (hh < HQ) {
        row = qkv + (long long)s * E + hh * HD;            w = qw;
        dh = qh + (long long)s * D + hh * HD;
        dl = ql + (long long)s * D + hh * HD;
    } else {
        row = qkv + (long long)s * E + D + (hh - HQ) * HD; w = kw;
        dh = kh + (long long)s * (G * HD) + (hh - HQ) * HD;
        dl = kl + (long long)s * (G * HD) + (hh - HQ) * HD;
    }

    const float2* row2 = (const float2*)row;
    float2 a = row2[lane], b = row2[lane + 32];
    float ss = a.x * a.x + a.y * a.y + b.x * b.x + b.y * b.y;
    #pragma unroll
    for (int o = 16; o; o >>= 1) ss += __shfl_xor_sync(0xFFFFFFFFu, ss, o);
    float r = rsqrtf(ss * (1.0f / 128.0f) + EPSF);

    const float2* w2 = (const float2*)w;
    float2 wa = w2[lane], wb = w2[lane + 32];
    float ax = (a.x * r) * wa.x, ay = (a.y * r) * wa.y;
    float bx = (b.x * r) * wb.x, by = (b.y * r) * wb.y;

    int base = s * (HD / 2);
    float c0 = cosT[base + lane],      s0 = sinT[base + lane];
    float c1 = cosT[base + lane + 32], s1 = sinT[base + lane + 32];

    float o0 = ax * c0 - ay * s0, o1 = ax * s0 + ay * c0;
    float o2 = bx * c1 - by * s1, o3 = bx * s1 + by * c1;

    bf16 h0, l0, h1, l1, h2, l2, h3, l3;
    split1(o0, h0, l0); split1(o1, h1, l1);
    split1(o2, h2, l2); split1(o3, h3, l3);
    ((bf162*)dh)[lane]      = bf162(h0, h1);
    ((bf162*)dl)[lane]      = bf162(l0, l1);
    ((bf162*)dh)[lane + 32] = bf162(h2, h3);
    ((bf162*)dl)[lane + 32] = bf162(l2, l3);
}

// ---------------------------------------------------------------------------
// Causal softmax reading fp32 scores, writing bf16 hi/lo probs.
// Zero-fills up to ceil128(s+1) (exactly the slack the K-limited PV reads).
// ---------------------------------------------------------------------------
__global__ void softmax_split_kernel(const float* __restrict__ scores,
                                     bf16* __restrict__ ph, bf16* __restrict__ pl) {
    int s = blockIdx.x, h = blockIdx.y;
    const float* row = scores + ((long long)h * S + s) * (long long)S;
    bf16* phr = ph + ((long long)h * S + s) * (long long)S;
    bf16* plr = pl + ((long long)h * S + s) * (long long)S;
    int n = s + 1;
    int nend = (n + 127) & ~127;
    int tid = threadIdx.x;

    float v[8];
    float mx = -FLT_MAX;
    #pragma unroll
    for (int i = 0; i < 8; i++) {
        int t = tid + i * 256;
        v[i] = (t < n) ? row[t] : -FLT_MAX;
        mx = fmaxf(mx, v[i]);
    }
    __shared__ float red[8];
    #pragma unroll
    for (int o = 16; o; o >>= 1) mx = fmaxf(mx, __shfl_xor_sync(0xFFFFFFFFu, mx, o));
    if ((tid & 31) == 0) red[tid >> 5] = mx;
    __syncthreads();
    mx = red[0];
    #pragma unroll
    for (int w = 1; w < 8; w++) mx = fmaxf(mx, red[w]);
    __syncthreads();

    float sum = 0.0f;
    #pragma unroll
    for (int i = 0; i < 8; i++) {
        int t = tid + i * 256;
        v[i] = (t < n) ? expf(v[i] - mx) : 0.0f;
        sum += v[i];
    }
    #pragma unroll
    for (int o = 16; o; o >>= 1) sum += __shfl_xor_sync(0xFFFFFFFFu, sum, o);
    if ((tid & 31) == 0) red[tid >> 5] = sum;
    __syncthreads();
    float tot = red[0];
    #pragma unroll
    for (int w = 1; w < 8; w++) tot += red[w];
    float inv = 1.0f / tot;

    #pragma unroll
    for (int i = 0; i < 8; i++) {
        int t = tid + i * 256;
        if (t < nend) {
            float pv = (t < n) ? v[i] * inv : 0.0f;
            bf16 hh, ll;
            split1(pv, hh, ll);
            phr[t] = hh; plr[t] = ll;
        }
    }
}

// ---------------------------------------------------------------------------
// Launch
// ---------------------------------------------------------------------------
extern "C" void kernel_launch(void* const* d_in, const int* in_sizes, int n_in,
                              void* d_out, int out_size) {
    const float* x     = (const float*)d_in[0];
    const float* w_qkv = (const float*)d_in[1];
    const float* w_out = (const float*)d_in[2];
    const float* qw    = (const float*)d_in[3];
    const float* kw    = (const float*)d_in[4];
    float* out = (float*)d_out;

    float *qkv, *scores, *cosT, *sinT;
    cudaGetSymbolAddress((void**)&qkv,    g_qkv);
    cudaGetSymbolAddress((void**)&scores, g_scores);
    cudaGetSymbolAddress((void**)&cosT,   g_cos);
    cudaGetSymbolAddress((void**)&sinT,   g_sin);
    bf16 *xh,*xl,*wqh,*wql,*woh,*wol,*qh,*ql,*kh,*kl,*vth,*vtl,*ph,*pl,*ah,*al;
    cudaGetSymbolAddress((void**)&xh,  g_xh);  cudaGetSymbolAddress((void**)&xl,  g_xl);
    cudaGetSymbolAddress((void**)&wqh, g_wqh); cudaGetSymbolAddress((void**)&wql, g_wql);
    cudaGetSymbolAddress((void**)&woh, g_woh); cudaGetSymbolAddress((void**)&wol, g_wol);
    cudaGetSymbolAddress((void**)&qh,  g_qh);  cudaGetSymbolAddress((void**)&ql,  g_ql);
    cudaGetSymbolAddress((void**)&kh,  g_kh);  cudaGetSymbolAddress((void**)&kl,  g_kl);
    cudaGetSymbolAddress((void**)&vth, g_vth); cudaGetSymbolAddress((void**)&vtl, g_vtl);
    cudaGetSymbolAddress((void**)&ph,  g_ph);  cudaGetSymbolAddress((void**)&pl,  g_pl);
    cudaGetSymbolAddress((void**)&ah,  g_ah);  cudaGetSymbolAddress((void**)&al,  g_al);

    const int SMEM = NSTG * STAGE_B;   // 81920
    cudaFuncSetAttribute(mma_gemm<0, 0>, cudaFuncAttributeMaxDynamicSharedMemorySize, SMEM);
    cudaFuncSetAttribute(mma_gemm<1, 0>, cudaFuncAttributeMaxDynamicSharedMemorySize, SMEM);
    cudaFuncSetAttribute(mma_gemm<2, 1>, cudaFuncAttributeMaxDynamicSharedMemorySize, SMEM);

    const float scale = 0.08838834764831845f;   // 1/sqrt(128)

    // #0 RoPE tables
    rope_table_kernel<<<(S * (HD / 2) + 255) / 256, 256>>>(cosT, sinT);

    // #1, #2: splits for QKV GEMM inputs
    {
        long long tx = (long long)S * D;
        split_kernel<<<(unsigned)((tx / 4 + 255) / 256), 256>>>(x, D, D, xh, xl, tx);
        long long tw = (long long)E * D;
        split_kernel<<<(unsigned)((tw / 4 + 255) / 256), 256>>>(w_qkv, D, D, wqh, wql, tw);
    }

    // #3 QKV projection: qkv = x @ w_qkv^T
    {
        dim3 grid(E / 128, S / 128, 1);
        mma_gemm<0, 0><<<grid, 256, SMEM>>>(xh, xl, wqh, wql, qkv, nullptr, nullptr,
                                            D, D, D, E, 0, 0, 0, 1, 1.0f);
    }

    // #4 RMSNorm + RoPE + split -> qh/ql, kh/kl
    rmsnorm_rope_split_kernel<<<S * (HQ + G) / 8, 256>>>(qkv, qw, kw, cosT, sinT,
                                                         qh, ql, kh, kl);

    // #5 scores[h] = scale * Q_h @ K_{h/4}^T  (causal tile skip)  [ncu target]
    {
        dim3 grid(S / 128, S / 128, HQ);
        mma_gemm<1, 0><<<grid, 256, SMEM>>>(qh, ql, kh, kl, scores, nullptr, nullptr,
                                            HD, D, G * HD, S,
                                            HD, HD, (long long)S * S, HG, scale);
    }

    // #6 V transpose + split (smem tiled, coalesced)
    {
        dim3 vg(S / 32, (G * HD) / 32);
        vsplit_kernel<<<vg, dim3(32, 8)>>>(qkv, vth, vtl);
    }

    // #7 causal softmax -> bf16 hi/lo probs
    {
        dim3 grid(S, HQ);
        softmax_split_kernel<<<grid, 256>>>(scores, ph, pl);
    }

    // #8 attn cols h*128.. = P_h @ V_{h/4}^T  (K-limited), emits ah/al bf16
    {
        dim3 grid(1, S / 128, HQ);
        mma_gemm<2, 1><<<grid, 256, SMEM>>>(ph, pl, vth, vtl, nullptr, ah, al,
                                            S, S, S, D,
                                            (long long)S * S, (long long)HD * S, HD, HG, 1.0f);
    }

    // #9 split w_out (independent; placed late so QK GEMM is launch #5)
    {
        long long to = (long long)D * D;
        split_kernel<<<(unsigned)((to / 4 + 255) / 256), 256>>>(w_out, D, D, woh, wol, to);
    }

    // #10 out = attn @ w_out^T
    {
        dim3 grid(D / 128, S / 128, 1);
        mma_gemm<0, 0><<<grid, 256, SMEM>>>(ah, al, woh, wol, out, nullptr, nullptr,
                                            D, D, D, D, 0, 0, 0, 1, 1.0f);
    }
}